// round 2
// baseline (speedup 1.0000x reference)
#include <cuda_runtime.h>

// Problem constants
constexpr int Bc  = 2;
constexpr int Sc  = 2048;
constexpr int Dc  = 2048;
constexpr int Hc  = 32;
constexpr int KVHc = 8;
constexpr int HDc = 64;
constexpr int Gc  = 4;            // q heads per kv head
constexpr float SCALE = 0.125f;   // 1/sqrt(64)

// Scratch (allocation-free rule: __device__ globals)
__device__ float g_Q[(size_t)Bc * Sc * Dc];           // [B*S, H*HD] = 32 MB
__device__ float g_K[(size_t)Bc * Sc * KVHc * HDc];   // [B*S, KVH*HD] = 8 MB
__device__ float g_V[(size_t)Bc * Sc * KVHc * HDc];   // 8 MB
__device__ float g_O[(size_t)Bc * Sc * Dc];           // attention output, 32 MB

// ---------------------------------------------------------------------------
// C = A(MxK) @ B(KxN), all row-major. Requires M%128==0, N%128==0, K%8==0.
// 128x128 block tile, 8 k-step, 256 threads, 8x8 per-thread microtile.
// ---------------------------------------------------------------------------
__global__ __launch_bounds__(256) void sgemm128(const float* __restrict__ A,
                                                const float* __restrict__ Bm,
                                                float* __restrict__ C,
                                                int M, int N, int K) {
    __shared__ float As[8][128];   // As[k][m]
    __shared__ float Bs[8][128];   // Bs[k][n]

    const int tid = threadIdx.x;
    const int tx = tid & 15;       // n-direction microtile index
    const int ty = tid >> 4;       // m-direction microtile index
    const int bx = blockIdx.x;     // n-block
    const int by = blockIdx.y;     // m-block

    // A stage: one float4 per thread: row = tid/2 (0..127), col = (tid&1)*4
    const int arow = tid >> 1;
    const int acol = (tid & 1) * 4;
    // B stage: one float4 per thread: row = tid/32 (0..7), col = (tid&31)*4
    const int brow = tid >> 5;
    const int bcol = (tid & 31) * 4;

    const float* Ap = A + (size_t)(by * 128 + arow) * K + acol;
    const float* Bp = Bm + (size_t)brow * N + bx * 128 + bcol;

    float c[8][8];
#pragma unroll
    for (int i = 0; i < 8; i++)
#pragma unroll
        for (int j = 0; j < 8; j++) c[i][j] = 0.f;

    for (int k0 = 0; k0 < K; k0 += 8) {
        float4 av = *(const float4*)(Ap + k0);
        float4 bv = *(const float4*)(Bp + (size_t)k0 * N);
        As[acol + 0][arow] = av.x;
        As[acol + 1][arow] = av.y;
        As[acol + 2][arow] = av.z;
        As[acol + 3][arow] = av.w;
        *(float4*)&Bs[brow][bcol] = bv;
        __syncthreads();

#pragma unroll
        for (int kk = 0; kk < 8; kk++) {
            float a[8], b[8];
            *(float4*)&a[0] = *(const float4*)&As[kk][ty * 8];
            *(float4*)&a[4] = *(const float4*)&As[kk][ty * 8 + 4];
            *(float4*)&b[0] = *(const float4*)&Bs[kk][tx * 8];
            *(float4*)&b[4] = *(const float4*)&Bs[kk][tx * 8 + 4];
#pragma unroll
            for (int i = 0; i < 8; i++)
#pragma unroll
                for (int j = 0; j < 8; j++) c[i][j] += a[i] * b[j];
        }
        __syncthreads();
    }

    float* Cp = C + (size_t)(by * 128 + ty * 8) * N + bx * 128 + tx * 8;
#pragma unroll
    for (int i = 0; i < 8; i++) {
        *(float4*)&Cp[(size_t)i * N]     = make_float4(c[i][0], c[i][1], c[i][2], c[i][3]);
        *(float4*)&Cp[(size_t)i * N + 4] = make_float4(c[i][4], c[i][5], c[i][6], c[i][7]);
    }
}

// ---------------------------------------------------------------------------
// Flash attention, fp32. One thread per query row. 128 queries per block.
// grid = (S/128, H, B). K/V tiles of 64 keys staged in smem.
// Reads g_Q [B*S, H*HD], g_K/g_V [B*S, KVH*HD]; writes g_O [B*S, H*HD].
// ---------------------------------------------------------------------------
__global__ __launch_bounds__(128) void flash_attn() {
    __shared__ float Ks[64][64];
    __shared__ float Vs[64][64];

    const int tid  = threadIdx.x;
    const int qidx = blockIdx.x * 128 + tid;   // query position in sequence
    const int h    = blockIdx.y;
    const int b    = blockIdx.z;
    const int g    = h / Gc;                   // kv head serving this q head

    // Load q row, fold in softmax scale
    const float* qp = g_Q + (size_t)(b * Sc + qidx) * Dc + h * HDc;
    float q[64];
#pragma unroll
    for (int i = 0; i < 16; i++) {
        float4 t = *(const float4*)(qp + i * 4);
        q[4 * i + 0] = t.x * SCALE;
        q[4 * i + 1] = t.y * SCALE;
        q[4 * i + 2] = t.z * SCALE;
        q[4 * i + 3] = t.w * SCALE;
    }

    float acc[64];
#pragma unroll
    for (int i = 0; i < 64; i++) acc[i] = 0.f;
    float m = -1e30f;
    float l = 0.f;

    const int lrow = tid >> 4;          // 0..7
    const int lcol = (tid & 15) * 4;    // 0..60

    for (int j0 = 0; j0 < Sc; j0 += 64) {
        // Stage 64 keys + values (each thread: 8 rows x 1 float4 per matrix)
#pragma unroll
        for (int r = 0; r < 8; r++) {
            int row = r * 8 + lrow;
            size_t gk = (size_t)(b * Sc + j0 + row) * (KVHc * HDc) + g * HDc + lcol;
            *(float4*)&Ks[row][lcol] = *(const float4*)(g_K + gk);
            *(float4*)&Vs[row][lcol] = *(const float4*)(g_V + gk);
        }
        __syncthreads();

        for (int j = 0; j < 64; j++) {
            float s = 0.f;
#pragma unroll
            for (int d = 0; d < 64; d++) s += q[d] * Ks[j][d];

            if (s <= m) {
                // common path: running max unchanged, no rescale
                float p = __expf(s - m);
                l += p;
#pragma unroll
                for (int d = 0; d < 64; d++) acc[d] += p * Vs[j][d];
            } else {
                // new max: rescale accumulators (p = exp(0) = 1)
                float corr = __expf(m - s);
                m = s;
                l = l * corr + 1.f;
#pragma unroll
                for (int d = 0; d < 64; d++) acc[d] = acc[d] * corr + Vs[j][d];
            }
        }
        __syncthreads();
    }

    float inv = 1.f / l;
    float* op = g_O + (size_t)(b * Sc + qidx) * Dc + h * HDc;
#pragma unroll
    for (int i = 0; i < 16; i++) {
        float4 t = make_float4(acc[4 * i + 0] * inv, acc[4 * i + 1] * inv,
                               acc[4 * i + 2] * inv, acc[4 * i + 3] * inv);
        *(float4*)(op + i * 4) = t;
    }
}

// ---------------------------------------------------------------------------
// Launch: QKV projections -> flash attention -> output projection
// Inputs (metadata order): hidden_states, Wq, Wk, Wv, Wo. Output fp32 [B,S,D].
// ---------------------------------------------------------------------------
extern "C" void kernel_launch(void* const* d_in, const int* in_sizes, int n_in,
                              void* d_out, int out_size) {
    const float* X  = (const float*)d_in[0];
    const float* Wq = (const float*)d_in[1];
    const float* Wk = (const float*)d_in[2];
    const float* Wv = (const float*)d_in[3];
    const float* Wo = (const float*)d_in[4];
    float* out = (float*)d_out;

    float *Qb, *Kb, *Vb, *Ob;
    cudaGetSymbolAddress((void**)&Qb, g_Q);
    cudaGetSymbolAddress((void**)&Kb, g_K);
    cudaGetSymbolAddress((void**)&Vb, g_V);
    cudaGetSymbolAddress((void**)&Ob, g_O);

    const int M = Bc * Sc;  // 4096

    // Q = X @ Wq : [4096,2048] x [2048,2048]
    sgemm128<<<dim3(Dc / 128, M / 128), 256>>>(X, Wq, Qb, M, Dc, Dc);
    // K = X @ Wk : [4096,2048] x [2048,512]
    sgemm128<<<dim3((KVHc * HDc) / 128, M / 128), 256>>>(X, Wk, Kb, M, KVHc * HDc, Dc);
    // V = X @ Wv
    sgemm128<<<dim3((KVHc * HDc) / 128, M / 128), 256>>>(X, Wv, Vb, M, KVHc * HDc, Dc);

    // Attention: grid (S/128, H, B), 128 threads (1 thread = 1 query)
    flash_attn<<<dim3(Sc / 128, Hc, Bc), 128>>>();

    // out = O @ Wo : [4096,2048] x [2048,2048]
    sgemm128<<<dim3(Dc / 128, M / 128), 256>>>(Ob, Wo, out, M, Dc, Dc);
}

// round 4
// speedup vs baseline: 1.5177x; 1.5177x over previous
#include <cuda_runtime.h>
#include <cstdint>

// Problem constants
constexpr int Bc  = 2;
constexpr int Sc  = 2048;
constexpr int Dc  = 2048;
constexpr int Hc  = 32;
constexpr int KVHc = 8;
constexpr int HDc = 64;
constexpr int Gc  = 4;            // q heads per kv head
constexpr float SCALE = 0.125f;   // 1/sqrt(64)

// Scratch (allocation-free rule: __device__ globals)
__device__ float g_Q[(size_t)Bc * Sc * Dc];
__device__ float g_K[(size_t)Bc * Sc * KVHc * HDc];
__device__ float g_V[(size_t)Bc * Sc * KVHc * HDc];
__device__ float g_O[(size_t)Bc * Sc * Dc];

// ---------------------------------------------------------------------------
// TF32 tensor-core GEMM: C = A(MxK) @ B(KxN), row-major fp32 in/out.
// 128x128 CTA tile, BK=16, 256 threads = 8 warps (2 x 4), warp tile 64x32,
// mma.sync.m16n8k8.tf32, cp.async double buffering.
// Requires M%128==0, N%128==0, K%16==0.
// ---------------------------------------------------------------------------
constexpr int ASTRIDE = 20;   // floats per A smem row (16 + 4 pad) -> conflict-free frags
constexpr int BSTRIDE = 136;  // floats per B smem row (128 + 8 pad) -> conflict-free frags
constexpr int ABUF = 128 * ASTRIDE;  // 2560 floats
constexpr int BBUF = 16 * BSTRIDE;   // 2176 floats

__device__ __forceinline__ void cp16(void* smem, const void* gmem) {
    uint32_t s = (uint32_t)__cvta_generic_to_shared(smem);
    asm volatile("cp.async.cg.shared.global [%0], [%1], 16;\n" :: "r"(s), "l"(gmem));
}
__device__ __forceinline__ void cp_commit() { asm volatile("cp.async.commit_group;\n"); }
__device__ __forceinline__ void cp_wait0()  { asm volatile("cp.async.wait_group 0;\n"); }

__device__ __forceinline__ uint32_t to_tf32(float f) {
    uint32_t r;
    asm("cvt.rna.tf32.f32 %0, %1;" : "=r"(r) : "f"(f));
    return r;
}

__device__ __forceinline__ void mma_tf32(float& c0, float& c1, float& c2, float& c3,
                                         uint32_t a0, uint32_t a1, uint32_t a2, uint32_t a3,
                                         uint32_t b0, uint32_t b1) {
    asm volatile(
        "mma.sync.aligned.m16n8k8.row.col.f32.tf32.tf32.f32 "
        "{%0,%1,%2,%3}, {%4,%5,%6,%7}, {%8,%9}, {%0,%1,%2,%3};\n"
        : "+f"(c0), "+f"(c1), "+f"(c2), "+f"(c3)
        : "r"(a0), "r"(a1), "r"(a2), "r"(a3), "r"(b0), "r"(b1));
}

__global__ __launch_bounds__(256) void tf32gemm(const float* __restrict__ A,
                                                const float* __restrict__ Bm,
                                                float* __restrict__ C,
                                                int M, int N, int K) {
    __shared__ float As[2][ABUF];
    __shared__ float Bs[2][BBUF];

    const int tid  = threadIdx.x;
    const int warp = tid >> 5;
    const int lane = tid & 31;
    const int grp  = lane >> 2;      // 0..7
    const int qid  = lane & 3;       // 0..3
    const int warpM = warp >> 2;     // 0..1  -> m offset 64*warpM
    const int warpN = warp & 3;      // 0..3  -> n offset 32*warpN
    const int bx = blockIdx.x;       // n block
    const int by = blockIdx.y;       // m block

    // Staging indices (2 chunks of 16B per thread, per matrix)
    // A tile 128x16: chunk c -> row=c/4, colchunk=c%4
    const int ac0 = tid, ac1 = tid + 256;
    // B tile 16x128: chunk c -> row=c/32, colchunk=c%32
    const int bc0 = tid, bc1 = tid + 256;

    const int numTiles = K / 16;

    auto load_tile = [&](int t, int s) {
        int k0 = t * 16;
        {
            int r = ac0 >> 2, cc = ac0 & 3;
            cp16(&As[s][r * ASTRIDE + cc * 4], A + (size_t)(by * 128 + r) * K + k0 + cc * 4);
            r = ac1 >> 2; cc = ac1 & 3;
            cp16(&As[s][r * ASTRIDE + cc * 4], A + (size_t)(by * 128 + r) * K + k0 + cc * 4);
        }
        {
            int r = bc0 >> 5, cc = bc0 & 31;
            cp16(&Bs[s][r * BSTRIDE + cc * 4], Bm + (size_t)(k0 + r) * N + bx * 128 + cc * 4);
            r = bc1 >> 5; cc = bc1 & 31;
            cp16(&Bs[s][r * BSTRIDE + cc * 4], Bm + (size_t)(k0 + r) * N + bx * 128 + cc * 4);
        }
        cp_commit();
    };

    float acc[4][4][4];  // [mfrag][nfrag][c0..c3]
#pragma unroll
    for (int i = 0; i < 4; i++)
#pragma unroll
        for (int j = 0; j < 4; j++)
#pragma unroll
            for (int r = 0; r < 4; r++) acc[i][j][r] = 0.f;

    load_tile(0, 0);

    for (int t = 0; t < numTiles; t++) {
        cp_wait0();
        __syncthreads();
        if (t + 1 < numTiles) load_tile(t + 1, (t + 1) & 1);

        const float* Asb = As[t & 1];
        const float* Bsb = Bs[t & 1];

#pragma unroll
        for (int kk = 0; kk < 16; kk += 8) {
            uint32_t af[4][4];
#pragma unroll
            for (int i = 0; i < 4; i++) {
                int mr = warpM * 64 + i * 16 + grp;
                af[i][0] = to_tf32(Asb[(mr)     * ASTRIDE + kk + qid]);
                af[i][1] = to_tf32(Asb[(mr + 8) * ASTRIDE + kk + qid]);
                af[i][2] = to_tf32(Asb[(mr)     * ASTRIDE + kk + qid + 4]);
                af[i][3] = to_tf32(Asb[(mr + 8) * ASTRIDE + kk + qid + 4]);
            }
            uint32_t bf[4][2];
#pragma unroll
            for (int j = 0; j < 4; j++) {
                int nc = warpN * 32 + j * 8 + grp;
                bf[j][0] = to_tf32(Bsb[(kk + qid)     * BSTRIDE + nc]);
                bf[j][1] = to_tf32(Bsb[(kk + qid + 4) * BSTRIDE + nc]);
            }
#pragma unroll
            for (int i = 0; i < 4; i++)
#pragma unroll
                for (int j = 0; j < 4; j++)
                    mma_tf32(acc[i][j][0], acc[i][j][1], acc[i][j][2], acc[i][j][3],
                             af[i][0], af[i][1], af[i][2], af[i][3],
                             bf[j][0], bf[j][1]);
        }
        __syncthreads();
    }

    // Store: warp tile 64x32; frag (i,j): rows grp/grp+8, cols 2*qid, 2*qid+1
#pragma unroll
    for (int i = 0; i < 4; i++) {
        int mr = by * 128 + warpM * 64 + i * 16 + grp;
#pragma unroll
        for (int j = 0; j < 4; j++) {
            int nc = bx * 128 + warpN * 32 + j * 8 + 2 * qid;
            float2 v0 = make_float2(acc[i][j][0], acc[i][j][1]);
            float2 v1 = make_float2(acc[i][j][2], acc[i][j][3]);
            *(float2*)&C[(size_t)mr * N + nc]       = v0;
            *(float2*)&C[(size_t)(mr + 8) * N + nc] = v1;
        }
    }
}

// ---------------------------------------------------------------------------
// Flash attention, fp32. One thread per query row. 128 queries per block.
// ---------------------------------------------------------------------------
__global__ __launch_bounds__(128) void flash_attn() {
    __shared__ float Ks[64][64];
    __shared__ float Vs[64][64];

    const int tid  = threadIdx.x;
    const int qidx = blockIdx.x * 128 + tid;
    const int h    = blockIdx.y;
    const int b    = blockIdx.z;
    const int g    = h / Gc;

    const float* qp = g_Q + (size_t)(b * Sc + qidx) * Dc + h * HDc;
    float q[64];
#pragma unroll
    for (int i = 0; i < 16; i++) {
        float4 t = *(const float4*)(qp + i * 4);
        q[4 * i + 0] = t.x * SCALE;
        q[4 * i + 1] = t.y * SCALE;
        q[4 * i + 2] = t.z * SCALE;
        q[4 * i + 3] = t.w * SCALE;
    }

    float acc[64];
#pragma unroll
    for (int i = 0; i < 64; i++) acc[i] = 0.f;
    float m = -1e30f;
    float l = 0.f;

    const int lrow = tid >> 4;
    const int lcol = (tid & 15) * 4;

    for (int j0 = 0; j0 < Sc; j0 += 64) {
#pragma unroll
        for (int r = 0; r < 8; r++) {
            int row = r * 8 + lrow;
            size_t gk = (size_t)(b * Sc + j0 + row) * (KVHc * HDc) + g * HDc + lcol;
            *(float4*)&Ks[row][lcol] = *(const float4*)(g_K + gk);
            *(float4*)&Vs[row][lcol] = *(const float4*)(g_V + gk);
        }
        __syncthreads();

        for (int j = 0; j < 64; j++) {
            float s = 0.f;
#pragma unroll
            for (int d = 0; d < 64; d++) s += q[d] * Ks[j][d];

            if (s <= m) {
                float p = __expf(s - m);
                l += p;
#pragma unroll
                for (int d = 0; d < 64; d++) acc[d] += p * Vs[j][d];
            } else {
                float corr = __expf(m - s);
                m = s;
                l = l * corr + 1.f;
#pragma unroll
                for (int d = 0; d < 64; d++) acc[d] = acc[d] * corr + Vs[j][d];
            }
        }
        __syncthreads();
    }

    float inv = 1.f / l;
    float* op = g_O + (size_t)(b * Sc + qidx) * Dc + h * HDc;
#pragma unroll
    for (int i = 0; i < 16; i++) {
        float4 t = make_float4(acc[4 * i + 0] * inv, acc[4 * i + 1] * inv,
                               acc[4 * i + 2] * inv, acc[4 * i + 3] * inv);
        *(float4*)(op + i * 4) = t;
    }
}

// ---------------------------------------------------------------------------
extern "C" void kernel_launch(void* const* d_in, const int* in_sizes, int n_in,
                              void* d_out, int out_size) {
    const float* X  = (const float*)d_in[0];
    const float* Wq = (const float*)d_in[1];
    const float* Wk = (const float*)d_in[2];
    const float* Wv = (const float*)d_in[3];
    const float* Wo = (const float*)d_in[4];
    float* out = (float*)d_out;

    float *Qb, *Kb, *Vb, *Ob;
    cudaGetSymbolAddress((void**)&Qb, g_Q);
    cudaGetSymbolAddress((void**)&Kb, g_K);
    cudaGetSymbolAddress((void**)&Vb, g_V);
    cudaGetSymbolAddress((void**)&Ob, g_O);

    const int M = Bc * Sc;  // 4096

    tf32gemm<<<dim3(Dc / 128, M / 128), 256>>>(X, Wq, Qb, M, Dc, Dc);
    tf32gemm<<<dim3((KVHc * HDc) / 128, M / 128), 256>>>(X, Wk, Kb, M, KVHc * HDc, Dc);
    tf32gemm<<<dim3((KVHc * HDc) / 128, M / 128), 256>>>(X, Wv, Vb, M, KVHc * HDc, Dc);

    flash_attn<<<dim3(Sc / 128, Hc, Bc), 128>>>();

    tf32gemm<<<dim3(Dc / 128, M / 128), 256>>>(Ob, Wo, out, M, Dc, Dc);
}

// round 7
// speedup vs baseline: 2.2204x; 1.4630x over previous
#include <cuda_runtime.h>
#include <cstdint>

// Problem constants
constexpr int Bc  = 2;
constexpr int Sc  = 2048;
constexpr int Dc  = 2048;
constexpr int Hc  = 32;
constexpr int KVHc = 8;
constexpr int HDc = 64;
constexpr float SCALE = 0.125f;   // 1/sqrt(64)
constexpr float LOG2E = 1.4426950408889634f;

// Scratch (allocation-free rule: __device__ globals)
__device__ float g_Q[(size_t)Bc * Sc * Dc];
__device__ float g_K[(size_t)Bc * Sc * KVHc * HDc];
__device__ float g_V[(size_t)Bc * Sc * KVHc * HDc];
__device__ float g_O[(size_t)Bc * Sc * Dc];

// ---------------------------------------------------------------------------
// Common PTX helpers
// ---------------------------------------------------------------------------
__device__ __forceinline__ void cp16(void* smem, const void* gmem) {
    uint32_t s = (uint32_t)__cvta_generic_to_shared(smem);
    asm volatile("cp.async.cg.shared.global [%0], [%1], 16;\n" :: "r"(s), "l"(gmem));
}
__device__ __forceinline__ void cp_commit() { asm volatile("cp.async.commit_group;\n"); }
__device__ __forceinline__ void cp_wait0()  { asm volatile("cp.async.wait_group 0;\n"); }

__device__ __forceinline__ uint32_t to_tf32(float f) {
    uint32_t r;
    asm("cvt.rna.tf32.f32 %0, %1;" : "=r"(r) : "f"(f));
    return r;
}
// Split fp32 into tf32 hi + tf32 lo (v - hi is exact in fp32)
__device__ __forceinline__ void split_tf32(float v, uint32_t& hi, uint32_t& lo) {
    hi = to_tf32(v);
    lo = to_tf32(v - __uint_as_float(hi));
}

__device__ __forceinline__ void mma_tf32(float& c0, float& c1, float& c2, float& c3,
                                         uint32_t a0, uint32_t a1, uint32_t a2, uint32_t a3,
                                         uint32_t b0, uint32_t b1) {
    asm volatile(
        "mma.sync.aligned.m16n8k8.row.col.f32.tf32.tf32.f32 "
        "{%0,%1,%2,%3}, {%4,%5,%6,%7}, {%8,%9}, {%0,%1,%2,%3};\n"
        : "+f"(c0), "+f"(c1), "+f"(c2), "+f"(c3)
        : "r"(a0), "r"(a1), "r"(a2), "r"(a3), "r"(b0), "r"(b1));
}

// Fast 2^y for y <= 0 (FMA pipe only, no MUFU). Rel err ~4e-5.
__device__ __forceinline__ float fast_exp2(float y) {
    y = fmaxf(y, -80.f);
    float t = y + 12582912.f;                 // round-to-nearest int via magic
    int k = __float_as_int(t) - 0x4B400000;   // integer part
    float f = y - (t - 12582912.f);           // frac in [-0.5, 0.5]
    float r = fmaf(f, 0.0096181291f, 0.0555041087f);
    r = fmaf(f, r, 0.2402265069f);
    r = fmaf(f, r, 0.6931471806f);
    r = fmaf(f, r, 1.0f);
    return __int_as_float(__float_as_int(r) + (k << 23));  // * 2^k
}

// ---------------------------------------------------------------------------
// TF32 tensor-core GEMM (unchanged from R2): C = A(MxK) @ B(KxN) fp32.
// ---------------------------------------------------------------------------
constexpr int ASTRIDE = 20;
constexpr int BSTRIDE = 136;
constexpr int ABUF = 128 * ASTRIDE;
constexpr int BBUF = 16 * BSTRIDE;

__global__ __launch_bounds__(256) void tf32gemm(const float* __restrict__ A,
                                                const float* __restrict__ Bm,
                                                float* __restrict__ C,
                                                int M, int N, int K) {
    __shared__ float As[2][ABUF];
    __shared__ float Bs[2][BBUF];

    const int tid  = threadIdx.x;
    const int warp = tid >> 5;
    const int lane = tid & 31;
    const int grp  = lane >> 2;
    const int qid  = lane & 3;
    const int warpM = warp >> 2;
    const int warpN = warp & 3;
    const int bx = blockIdx.x;
    const int by = blockIdx.y;

    const int ac0 = tid, ac1 = tid + 256;
    const int bc0 = tid, bc1 = tid + 256;
    const int numTiles = K / 16;

    auto load_tile = [&](int t, int s) {
        int k0 = t * 16;
        {
            int r = ac0 >> 2, cc = ac0 & 3;
            cp16(&As[s][r * ASTRIDE + cc * 4], A + (size_t)(by * 128 + r) * K + k0 + cc * 4);
            r = ac1 >> 2; cc = ac1 & 3;
            cp16(&As[s][r * ASTRIDE + cc * 4], A + (size_t)(by * 128 + r) * K + k0 + cc * 4);
        }
        {
            int r = bc0 >> 5, cc = bc0 & 31;
            cp16(&Bs[s][r * BSTRIDE + cc * 4], Bm + (size_t)(k0 + r) * N + bx * 128 + cc * 4);
            r = bc1 >> 5; cc = bc1 & 31;
            cp16(&Bs[s][r * BSTRIDE + cc * 4], Bm + (size_t)(k0 + r) * N + bx * 128 + cc * 4);
        }
        cp_commit();
    };

    float acc[4][4][4];
#pragma unroll
    for (int i = 0; i < 4; i++)
#pragma unroll
        for (int j = 0; j < 4; j++)
#pragma unroll
            for (int r = 0; r < 4; r++) acc[i][j][r] = 0.f;

    load_tile(0, 0);

    for (int t = 0; t < numTiles; t++) {
        cp_wait0();
        __syncthreads();
        if (t + 1 < numTiles) load_tile(t + 1, (t + 1) & 1);

        const float* Asb = As[t & 1];
        const float* Bsb = Bs[t & 1];

#pragma unroll
        for (int kk = 0; kk < 16; kk += 8) {
            uint32_t af[4][4];
#pragma unroll
            for (int i = 0; i < 4; i++) {
                int mr = warpM * 64 + i * 16 + grp;
                af[i][0] = to_tf32(Asb[(mr)     * ASTRIDE + kk + qid]);
                af[i][1] = to_tf32(Asb[(mr + 8) * ASTRIDE + kk + qid]);
                af[i][2] = to_tf32(Asb[(mr)     * ASTRIDE + kk + qid + 4]);
                af[i][3] = to_tf32(Asb[(mr + 8) * ASTRIDE + kk + qid + 4]);
            }
            uint32_t bf[4][2];
#pragma unroll
            for (int j = 0; j < 4; j++) {
                int nc = warpN * 32 + j * 8 + grp;
                bf[j][0] = to_tf32(Bsb[(kk + qid)     * BSTRIDE + nc]);
                bf[j][1] = to_tf32(Bsb[(kk + qid + 4) * BSTRIDE + nc]);
            }
#pragma unroll
            for (int i = 0; i < 4; i++)
#pragma unroll
                for (int j = 0; j < 4; j++)
                    mma_tf32(acc[i][j][0], acc[i][j][1], acc[i][j][2], acc[i][j][3],
                             af[i][0], af[i][1], af[i][2], af[i][3],
                             bf[j][0], bf[j][1]);
        }
        __syncthreads();
    }

#pragma unroll
    for (int i = 0; i < 4; i++) {
        int mr = by * 128 + warpM * 64 + i * 16 + grp;
#pragma unroll
        for (int j = 0; j < 4; j++) {
            int nc = bx * 128 + warpN * 32 + j * 8 + 2 * qid;
            *(float2*)&C[(size_t)mr * N + nc]       = make_float2(acc[i][j][0], acc[i][j][1]);
            *(float2*)&C[(size_t)(mr + 8) * N + nc] = make_float2(acc[i][j][2], acc[i][j][3]);
        }
    }
}

// ---------------------------------------------------------------------------
// Tensor-core flash attention, 3xTF32 compensated, software exp2.
// CTA: 64 queries x 1 head, 128 threads (4 warps; warp w owns S rows 16w..16w+15).
// grid = (S/64, H, B). K/V tiles 64 keys, single-buffered cp.async.
// ---------------------------------------------------------------------------
constexpr int QSTR = 68;   // conflict-free: (68*g)%32 = 4g
constexpr int KSTR = 68;
constexpr int VSTR = 72;   // b-frag reads rows kk+qid: (72*q)%32 = 8q
constexpr int PSTR = 68;
constexpr int ATT_SMEM = (64 * QSTR + 64 * KSTR + 64 * VSTR + 64 * PSTR) * 4;  // 70656 B

__global__ __launch_bounds__(128) void flash_attn_tc() {
    extern __shared__ float smf[];
    float* Qs = smf;
    float* Ks = Qs + 64 * QSTR;
    float* Vs = Ks + 64 * KSTR;
    float* Ps = Vs + 64 * VSTR;

    const int tid  = threadIdx.x;
    const int warp = tid >> 5;
    const int lane = tid & 31;
    const int grp  = lane >> 2;
    const int qid  = lane & 3;
    const int h = blockIdx.y, b = blockIdx.z;
    const int g = h >> 2;                 // kv head
    const int q0blk = blockIdx.x * 64;

    // Load Q tile (64x64), fold SCALE*log2(e) so scores live in log2 domain
    {
        const float sc = SCALE * LOG2E;
        int r = tid >> 1, ch = (tid & 1) * 32;   // 2 threads/row, 32 floats each
        const float* qp = g_Q + (size_t)(b * Sc + q0blk + r) * Dc + h * HDc + ch;
        float* qs = Qs + r * QSTR + ch;
#pragma unroll
        for (int i = 0; i < 8; i++) {
            float4 t = *(const float4*)(qp + i * 4);
            qs[i * 4 + 0] = t.x * sc; qs[i * 4 + 1] = t.y * sc;
            qs[i * 4 + 2] = t.z * sc; qs[i * 4 + 3] = t.w * sc;
        }
    }

    const int r0 = warp * 16 + grp;    // this thread's S/O row pair: r0, r0+8

    float oacc[8][4];
#pragma unroll
    for (int j = 0; j < 8; j++)
#pragma unroll
        for (int r = 0; r < 4; r++) oacc[j][r] = 0.f;
    float m0 = -1e30f, m1 = -1e30f, l0 = 0.f, l1 = 0.f;

    for (int t = 0; t < 32; t++) {
        // Stage K/V tile t (64x64 each), 8 cp16 per thread per matrix
#pragma unroll
        for (int i = 0; i < 8; i++) {
            int c = tid + i * 128;             // 0..1023
            int row = c >> 4, cc = (c & 15) * 4;
            size_t gb = (size_t)(b * Sc + t * 64 + row) * (KVHc * HDc) + g * HDc + cc;
            cp16(&Ks[row * KSTR + cc], g_K + gb);
            cp16(&Vs[row * VSTR + cc], g_V + gb);
        }
        cp_commit();
        cp_wait0();
        __syncthreads();

        // ---- S = Q @ K^T (3xTF32) ----
        float sacc[8][4];
#pragma unroll
        for (int j = 0; j < 8; j++)
#pragma unroll
            for (int r = 0; r < 4; r++) sacc[j][r] = 0.f;

#pragma unroll
        for (int kk = 0; kk < 64; kk += 8) {
            uint32_t ah[4], al[4];
            split_tf32(Qs[(r0)     * QSTR + kk + qid],     ah[0], al[0]);
            split_tf32(Qs[(r0 + 8) * QSTR + kk + qid],     ah[1], al[1]);
            split_tf32(Qs[(r0)     * QSTR + kk + qid + 4], ah[2], al[2]);
            split_tf32(Qs[(r0 + 8) * QSTR + kk + qid + 4], ah[3], al[3]);
#pragma unroll
            for (int j = 0; j < 8; j++) {
                int n = j * 8 + grp;
                uint32_t bh0, bl0, bh1, bl1;
                split_tf32(Ks[n * KSTR + kk + qid],     bh0, bl0);
                split_tf32(Ks[n * KSTR + kk + qid + 4], bh1, bl1);
                mma_tf32(sacc[j][0], sacc[j][1], sacc[j][2], sacc[j][3],
                         ah[0], ah[1], ah[2], ah[3], bh0, bh1);
                mma_tf32(sacc[j][0], sacc[j][1], sacc[j][2], sacc[j][3],
                         ah[0], ah[1], ah[2], ah[3], bl0, bl1);
                mma_tf32(sacc[j][0], sacc[j][1], sacc[j][2], sacc[j][3],
                         al[0], al[1], al[2], al[3], bh0, bh1);
            }
        }

        // ---- online softmax (log2 domain), P -> smem ----
        {
            float mx0 = -1e30f, mx1 = -1e30f;
#pragma unroll
            for (int j = 0; j < 8; j++) {
                mx0 = fmaxf(mx0, fmaxf(sacc[j][0], sacc[j][1]));
                mx1 = fmaxf(mx1, fmaxf(sacc[j][2], sacc[j][3]));
            }
            mx0 = fmaxf(mx0, __shfl_xor_sync(0xffffffff, mx0, 1));
            mx0 = fmaxf(mx0, __shfl_xor_sync(0xffffffff, mx0, 2));
            mx1 = fmaxf(mx1, __shfl_xor_sync(0xffffffff, mx1, 1));
            mx1 = fmaxf(mx1, __shfl_xor_sync(0xffffffff, mx1, 2));

            float mn0 = fmaxf(m0, mx0), mn1 = fmaxf(m1, mx1);
            float c0 = fast_exp2(m0 - mn0), c1 = fast_exp2(m1 - mn1);
            m0 = mn0; m1 = mn1;

            float s0 = 0.f, s1 = 0.f;
#pragma unroll
            for (int j = 0; j < 8; j++) {
                float p00 = fast_exp2(sacc[j][0] - mn0);
                float p01 = fast_exp2(sacc[j][1] - mn0);
                float p10 = fast_exp2(sacc[j][2] - mn1);
                float p11 = fast_exp2(sacc[j][3] - mn1);
                s0 += p00 + p01; s1 += p10 + p11;
                *(float2*)&Ps[(r0)     * PSTR + j * 8 + 2 * qid] = make_float2(p00, p01);
                *(float2*)&Ps[(r0 + 8) * PSTR + j * 8 + 2 * qid] = make_float2(p10, p11);
                oacc[j][0] *= c0; oacc[j][1] *= c0;
                oacc[j][2] *= c1; oacc[j][3] *= c1;
            }
            s0 += __shfl_xor_sync(0xffffffff, s0, 1);
            s0 += __shfl_xor_sync(0xffffffff, s0, 2);
            s1 += __shfl_xor_sync(0xffffffff, s1, 1);
            s1 += __shfl_xor_sync(0xffffffff, s1, 2);
            l0 = l0 * c0 + s0;
            l1 = l1 * c1 + s1;
        }
        __syncwarp();

        // ---- O += P @ V (3xTF32) ----
#pragma unroll
        for (int kk = 0; kk < 64; kk += 8) {
            uint32_t ah[4], al[4];
            split_tf32(Ps[(r0)     * PSTR + kk + qid],     ah[0], al[0]);
            split_tf32(Ps[(r0 + 8) * PSTR + kk + qid],     ah[1], al[1]);
            split_tf32(Ps[(r0)     * PSTR + kk + qid + 4], ah[2], al[2]);
            split_tf32(Ps[(r0 + 8) * PSTR + kk + qid + 4], ah[3], al[3]);
#pragma unroll
            for (int j = 0; j < 8; j++) {
                int n = j * 8 + grp;
                uint32_t bh0, bl0, bh1, bl1;
                split_tf32(Vs[(kk + qid)     * VSTR + n], bh0, bl0);
                split_tf32(Vs[(kk + qid + 4) * VSTR + n], bh1, bl1);
                mma_tf32(oacc[j][0], oacc[j][1], oacc[j][2], oacc[j][3],
                         ah[0], ah[1], ah[2], ah[3], bh0, bh1);
                mma_tf32(oacc[j][0], oacc[j][1], oacc[j][2], oacc[j][3],
                         ah[0], ah[1], ah[2], ah[3], bl0, bl1);
                mma_tf32(oacc[j][0], oacc[j][1], oacc[j][2], oacc[j][3],
                         al[0], al[1], al[2], al[3], bh0, bh1);
            }
        }
        __syncthreads();   // all reads of Ks/Vs/Ps done before next stage
    }

    // Epilogue: normalize and write O rows r0, r0+8
    {
        float inv0 = 1.f / l0, inv1 = 1.f / l1;
        float* op0 = g_O + (size_t)(b * Sc + q0blk + r0) * Dc + h * HDc;
        float* op1 = g_O + (size_t)(b * Sc + q0blk + r0 + 8) * Dc + h * HDc;
#pragma unroll
        for (int j = 0; j < 8; j++) {
            *(float2*)&op0[j * 8 + 2 * qid] = make_float2(oacc[j][0] * inv0, oacc[j][1] * inv0);
            *(float2*)&op1[j * 8 + 2 * qid] = make_float2(oacc[j][2] * inv1, oacc[j][3] * inv1);
        }
    }
}

// ---------------------------------------------------------------------------
extern "C" void kernel_launch(void* const* d_in, const int* in_sizes, int n_in,
                              void* d_out, int out_size) {
    const float* X  = (const float*)d_in[0];
    const float* Wq = (const float*)d_in[1];
    const float* Wk = (const float*)d_in[2];
    const float* Wv = (const float*)d_in[3];
    const float* Wo = (const float*)d_in[4];
    float* out = (float*)d_out;

    float *Qb, *Kb, *Vb, *Ob;
    cudaGetSymbolAddress((void**)&Qb, g_Q);
    cudaGetSymbolAddress((void**)&Kb, g_K);
    cudaGetSymbolAddress((void**)&Vb, g_V);
    cudaGetSymbolAddress((void**)&Ob, g_O);

    cudaFuncSetAttribute(flash_attn_tc, cudaFuncAttributeMaxDynamicSharedMemorySize, ATT_SMEM);

    const int M = Bc * Sc;  // 4096

    tf32gemm<<<dim3(Dc / 128, M / 128), 256>>>(X, Wq, Qb, M, Dc, Dc);
    tf32gemm<<<dim3((KVHc * HDc) / 128, M / 128), 256>>>(X, Wk, Kb, M, KVHc * HDc, Dc);
    tf32gemm<<<dim3((KVHc * HDc) / 128, M / 128), 256>>>(X, Wv, Vb, M, KVHc * HDc, Dc);

    flash_attn_tc<<<dim3(Sc / 64, Hc, Bc), 128, ATT_SMEM>>>();

    tf32gemm<<<dim3(Dc / 128, M / 128), 256>>>(Ob, Wo, out, M, Dc, Dc);
}

// round 8
// speedup vs baseline: 2.5071x; 1.1291x over previous
#include <cuda_runtime.h>
#include <cstdint>

// Problem constants
constexpr int Bc  = 2;
constexpr int Sc  = 2048;
constexpr int Dc  = 2048;
constexpr int Hc  = 32;
constexpr int KVHc = 8;
constexpr int HDc = 64;
constexpr float SCALE = 0.125f;   // 1/sqrt(64)
constexpr float LOG2E = 1.4426950408889634f;

// Scratch (allocation-free rule: __device__ globals)
// Q/K/V stored PRE-SPLIT as tf32 (hi, lo) bit patterns by the GEMM epilogues.
__device__ uint32_t g_Qhi[(size_t)Bc * Sc * Dc];
__device__ uint32_t g_Qlo[(size_t)Bc * Sc * Dc];
__device__ uint32_t g_Khi[(size_t)Bc * Sc * KVHc * HDc];
__device__ uint32_t g_Klo[(size_t)Bc * Sc * KVHc * HDc];
__device__ uint32_t g_Vhi[(size_t)Bc * Sc * KVHc * HDc];
__device__ uint32_t g_Vlo[(size_t)Bc * Sc * KVHc * HDc];
__device__ float    g_O  [(size_t)Bc * Sc * Dc];

// ---------------------------------------------------------------------------
// Common PTX helpers
// ---------------------------------------------------------------------------
__device__ __forceinline__ void cp16(void* smem, const void* gmem) {
    uint32_t s = (uint32_t)__cvta_generic_to_shared(smem);
    asm volatile("cp.async.cg.shared.global [%0], [%1], 16;\n" :: "r"(s), "l"(gmem));
}
__device__ __forceinline__ void cp_commit() { asm volatile("cp.async.commit_group;\n"); }
__device__ __forceinline__ void cp_wait0()  { asm volatile("cp.async.wait_group 0;\n"); }

__device__ __forceinline__ uint32_t to_tf32(float f) {
    uint32_t r;
    asm("cvt.rna.tf32.f32 %0, %1;" : "=r"(r) : "f"(f));
    return r;
}
__device__ __forceinline__ void split_tf32(float v, uint32_t& hi, uint32_t& lo) {
    hi = to_tf32(v);
    lo = to_tf32(v - __uint_as_float(hi));
}

__device__ __forceinline__ void mma_tf32(float& c0, float& c1, float& c2, float& c3,
                                         uint32_t a0, uint32_t a1, uint32_t a2, uint32_t a3,
                                         uint32_t b0, uint32_t b1) {
    asm volatile(
        "mma.sync.aligned.m16n8k8.row.col.f32.tf32.tf32.f32 "
        "{%0,%1,%2,%3}, {%4,%5,%6,%7}, {%8,%9}, {%0,%1,%2,%3};\n"
        : "+f"(c0), "+f"(c1), "+f"(c2), "+f"(c3)
        : "r"(a0), "r"(a1), "r"(a2), "r"(a3), "r"(b0), "r"(b1));
}

// Fast 2^y for y <= 0 (FMA pipe only, no MUFU). Rel err ~4e-5.
__device__ __forceinline__ float fast_exp2(float y) {
    y = fmaxf(y, -80.f);
    float t = y + 12582912.f;
    int k = __float_as_int(t) - 0x4B400000;
    float f = y - (t - 12582912.f);
    float r = fmaf(f, 0.0096181291f, 0.0555041087f);
    r = fmaf(f, r, 0.2402265069f);
    r = fmaf(f, r, 0.6931471806f);
    r = fmaf(f, r, 1.0f);
    return __int_as_float(__float_as_int(r) + (k << 23));
}

// ---------------------------------------------------------------------------
// TF32 GEMM core (128x128 tile, BK=16, 8 warps, m16n8k8). Two epilogues:
//   tf32gemm       : C fp32
//   tf32gemm_split : (C*prescale) split into tf32 hi/lo u32 arrays
// ---------------------------------------------------------------------------
constexpr int ASTRIDE = 20;
constexpr int BSTRIDE = 136;
constexpr int ABUF = 128 * ASTRIDE;
constexpr int BBUF = 16 * BSTRIDE;

#define GEMM_BODY                                                                   \
    __shared__ float As[2][ABUF];                                                   \
    __shared__ float Bs[2][BBUF];                                                   \
    const int tid  = threadIdx.x;                                                   \
    const int warp = tid >> 5;                                                      \
    const int lane = tid & 31;                                                      \
    const int grp  = lane >> 2;                                                     \
    const int qid  = lane & 3;                                                      \
    const int warpM = warp >> 2;                                                    \
    const int warpN = warp & 3;                                                     \
    const int bx = blockIdx.x;                                                      \
    const int by = blockIdx.y;                                                      \
    const int numTiles = K / 16;                                                    \
    auto load_tile = [&](int t, int s) {                                            \
        int k0 = t * 16;                                                            \
        {                                                                           \
            int r = tid >> 2, cc = tid & 3;                                         \
            cp16(&As[s][r * ASTRIDE + cc * 4],                                      \
                 A + (size_t)(by * 128 + r) * K + k0 + cc * 4);                     \
            r = (tid + 256) >> 2; cc = (tid + 256) & 3;                             \
            cp16(&As[s][r * ASTRIDE + cc * 4],                                      \
                 A + (size_t)(by * 128 + r) * K + k0 + cc * 4);                     \
        }                                                                           \
        {                                                                           \
            int r = tid >> 5, cc = tid & 31;                                        \
            cp16(&Bs[s][r * BSTRIDE + cc * 4],                                      \
                 Bm + (size_t)(k0 + r) * N + bx * 128 + cc * 4);                    \
            r = (tid + 256) >> 5; cc = (tid + 256) & 31;                            \
            cp16(&Bs[s][r * BSTRIDE + cc * 4],                                      \
                 Bm + (size_t)(k0 + r) * N + bx * 128 + cc * 4);                    \
        }                                                                           \
        cp_commit();                                                                \
    };                                                                              \
    float acc[4][4][4];                                                             \
    _Pragma("unroll")                                                               \
    for (int i = 0; i < 4; i++)                                                     \
        _Pragma("unroll")                                                           \
        for (int j = 0; j < 4; j++)                                                 \
            _Pragma("unroll")                                                       \
            for (int r = 0; r < 4; r++) acc[i][j][r] = 0.f;                         \
    load_tile(0, 0);                                                                \
    for (int t = 0; t < numTiles; t++) {                                            \
        cp_wait0();                                                                 \
        __syncthreads();                                                            \
        if (t + 1 < numTiles) load_tile(t + 1, (t + 1) & 1);                        \
        const float* Asb = As[t & 1];                                               \
        const float* Bsb = Bs[t & 1];                                               \
        _Pragma("unroll")                                                           \
        for (int kk = 0; kk < 16; kk += 8) {                                        \
            uint32_t af[4][4];                                                      \
            _Pragma("unroll")                                                       \
            for (int i = 0; i < 4; i++) {                                           \
                int mr = warpM * 64 + i * 16 + grp;                                 \
                af[i][0] = to_tf32(Asb[(mr)     * ASTRIDE + kk + qid]);             \
                af[i][1] = to_tf32(Asb[(mr + 8) * ASTRIDE + kk + qid]);             \
                af[i][2] = to_tf32(Asb[(mr)     * ASTRIDE + kk + qid + 4]);         \
                af[i][3] = to_tf32(Asb[(mr + 8) * ASTRIDE + kk + qid + 4]);         \
            }                                                                       \
            uint32_t bf[4][2];                                                      \
            _Pragma("unroll")                                                       \
            for (int j = 0; j < 4; j++) {                                           \
                int nc = warpN * 32 + j * 8 + grp;                                  \
                bf[j][0] = to_tf32(Bsb[(kk + qid)     * BSTRIDE + nc]);             \
                bf[j][1] = to_tf32(Bsb[(kk + qid + 4) * BSTRIDE + nc]);             \
            }                                                                       \
            _Pragma("unroll")                                                       \
            for (int i = 0; i < 4; i++)                                             \
                _Pragma("unroll")                                                   \
                for (int j = 0; j < 4; j++)                                         \
                    mma_tf32(acc[i][j][0], acc[i][j][1], acc[i][j][2], acc[i][j][3],\
                             af[i][0], af[i][1], af[i][2], af[i][3],                \
                             bf[j][0], bf[j][1]);                                   \
        }                                                                           \
        __syncthreads();                                                            \
    }

__global__ __launch_bounds__(256) void tf32gemm(const float* __restrict__ A,
                                                const float* __restrict__ Bm,
                                                float* __restrict__ C,
                                                int M, int N, int K) {
    GEMM_BODY
#pragma unroll
    for (int i = 0; i < 4; i++) {
        int mr = by * 128 + warpM * 64 + i * 16 + grp;
#pragma unroll
        for (int j = 0; j < 4; j++) {
            int nc = bx * 128 + warpN * 32 + j * 8 + 2 * qid;
            *(float2*)&C[(size_t)mr * N + nc]       = make_float2(acc[i][j][0], acc[i][j][1]);
            *(float2*)&C[(size_t)(mr + 8) * N + nc] = make_float2(acc[i][j][2], acc[i][j][3]);
        }
    }
}

__global__ __launch_bounds__(256) void tf32gemm_split(const float* __restrict__ A,
                                                      const float* __restrict__ Bm,
                                                      uint32_t* __restrict__ Chi,
                                                      uint32_t* __restrict__ Clo,
                                                      float prescale,
                                                      int M, int N, int K) {
    GEMM_BODY
#pragma unroll
    for (int i = 0; i < 4; i++) {
        int mr = by * 128 + warpM * 64 + i * 16 + grp;
#pragma unroll
        for (int j = 0; j < 4; j++) {
            int nc = bx * 128 + warpN * 32 + j * 8 + 2 * qid;
            uint32_t h[4], l[4];
#pragma unroll
            for (int r = 0; r < 4; r++) split_tf32(acc[i][j][r] * prescale, h[r], l[r]);
            *(uint2*)&Chi[(size_t)mr * N + nc]       = make_uint2(h[0], h[1]);
            *(uint2*)&Clo[(size_t)mr * N + nc]       = make_uint2(l[0], l[1]);
            *(uint2*)&Chi[(size_t)(mr + 8) * N + nc] = make_uint2(h[2], h[3]);
            *(uint2*)&Clo[(size_t)(mr + 8) * N + nc] = make_uint2(l[2], l[3]);
        }
    }
}

// ---------------------------------------------------------------------------
// Tensor-core flash attention, 3xTF32, pre-split inputs.
// CTA: 64 queries x 1 head, 128 threads (4 warps). Q pre-split in registers.
// K/V pre-split, staged hi/lo via cp.async. P split once at write.
// ---------------------------------------------------------------------------
constexpr int KSTR = 68;
constexpr int VSTR = 72;
constexpr int PSTR = 68;
constexpr int ATT_SMEM = (2 * 64 * KSTR + 2 * 64 * VSTR + 2 * 64 * PSTR) * 4;  // 106496 B

__global__ __launch_bounds__(128) void flash_attn_tc2() {
    extern __shared__ uint32_t smu[];
    uint32_t* Khi = smu;
    uint32_t* Klo = Khi + 64 * KSTR;
    uint32_t* Vhi = Klo + 64 * KSTR;
    uint32_t* Vlo = Vhi + 64 * VSTR;
    uint32_t* Phi = Vlo + 64 * VSTR;
    uint32_t* Plo = Phi + 64 * PSTR;

    const int tid  = threadIdx.x;
    const int warp = tid >> 5;
    const int lane = tid & 31;
    const int grp  = lane >> 2;
    const int qid  = lane & 3;
    const int h = blockIdx.y, b = blockIdx.z;
    const int g = h >> 2;
    const int q0blk = blockIdx.x * 64;

    const int r0 = warp * 16 + grp;    // this thread's S/O row pair: r0, r0+8

    // Q fragments (pre-scaled, pre-split by GEMM epilogue) -> registers, loop-invariant
    uint32_t qh[8][4], ql[8][4];
    {
        const size_t base = (size_t)(b * Sc + q0blk + r0) * Dc + h * HDc;
        const size_t row8 = (size_t)8 * Dc;
#pragma unroll
        for (int k = 0; k < 8; k++) {
            int c0 = k * 8 + qid;
            qh[k][0] = g_Qhi[base + c0];          ql[k][0] = g_Qlo[base + c0];
            qh[k][1] = g_Qhi[base + row8 + c0];   ql[k][1] = g_Qlo[base + row8 + c0];
            qh[k][2] = g_Qhi[base + c0 + 4];      ql[k][2] = g_Qlo[base + c0 + 4];
            qh[k][3] = g_Qhi[base + row8 + c0 + 4]; ql[k][3] = g_Qlo[base + row8 + c0 + 4];
        }
    }

    float oacc[8][4];
#pragma unroll
    for (int j = 0; j < 8; j++)
#pragma unroll
        for (int r = 0; r < 4; r++) oacc[j][r] = 0.f;
    float m0 = -1e30f, m1 = -1e30f, l0 = 0.f, l1 = 0.f;

    for (int t = 0; t < 32; t++) {
        // Stage pre-split K/V tile (4 arrays x 64x64 u32), 32 cp16/thread
#pragma unroll
        for (int i = 0; i < 8; i++) {
            int c = tid + i * 128;
            int row = c >> 4, cc = (c & 15) * 4;
            size_t gb = (size_t)(b * Sc + t * 64 + row) * (KVHc * HDc) + g * HDc + cc;
            cp16(&Khi[row * KSTR + cc], g_Khi + gb);
            cp16(&Klo[row * KSTR + cc], g_Klo + gb);
            cp16(&Vhi[row * VSTR + cc], g_Vhi + gb);
            cp16(&Vlo[row * VSTR + cc], g_Vlo + gb);
        }
        cp_commit();
        cp_wait0();
        __syncthreads();

        // ---- S = Q @ K^T (3xTF32, all operands pre-split) ----
        float sacc[8][4];
#pragma unroll
        for (int j = 0; j < 8; j++)
#pragma unroll
            for (int r = 0; r < 4; r++) sacc[j][r] = 0.f;

#pragma unroll
        for (int k = 0; k < 8; k++) {
            const int kk = k * 8;
#pragma unroll
            for (int j = 0; j < 8; j++) {
                int n = j * 8 + grp;
                uint32_t bh0 = Khi[n * KSTR + kk + qid];
                uint32_t bl0 = Klo[n * KSTR + kk + qid];
                uint32_t bh1 = Khi[n * KSTR + kk + qid + 4];
                uint32_t bl1 = Klo[n * KSTR + kk + qid + 4];
                mma_tf32(sacc[j][0], sacc[j][1], sacc[j][2], sacc[j][3],
                         qh[k][0], qh[k][1], qh[k][2], qh[k][3], bh0, bh1);
                mma_tf32(sacc[j][0], sacc[j][1], sacc[j][2], sacc[j][3],
                         qh[k][0], qh[k][1], qh[k][2], qh[k][3], bl0, bl1);
                mma_tf32(sacc[j][0], sacc[j][1], sacc[j][2], sacc[j][3],
                         ql[k][0], ql[k][1], ql[k][2], ql[k][3], bh0, bh1);
            }
        }

        // ---- online softmax (log2 domain), P split once -> Phi/Plo ----
        {
            float mx0 = -1e30f, mx1 = -1e30f;
#pragma unroll
            for (int j = 0; j < 8; j++) {
                mx0 = fmaxf(mx0, fmaxf(sacc[j][0], sacc[j][1]));
                mx1 = fmaxf(mx1, fmaxf(sacc[j][2], sacc[j][3]));
            }
            mx0 = fmaxf(mx0, __shfl_xor_sync(0xffffffff, mx0, 1));
            mx0 = fmaxf(mx0, __shfl_xor_sync(0xffffffff, mx0, 2));
            mx1 = fmaxf(mx1, __shfl_xor_sync(0xffffffff, mx1, 1));
            mx1 = fmaxf(mx1, __shfl_xor_sync(0xffffffff, mx1, 2));

            float mn0 = fmaxf(m0, mx0), mn1 = fmaxf(m1, mx1);
            float c0 = fast_exp2(m0 - mn0), c1 = fast_exp2(m1 - mn1);
            m0 = mn0; m1 = mn1;

            float s0 = 0.f, s1 = 0.f;
#pragma unroll
            for (int j = 0; j < 8; j++) {
                float p00 = fast_exp2(sacc[j][0] - mn0);
                float p01 = fast_exp2(sacc[j][1] - mn0);
                float p10 = fast_exp2(sacc[j][2] - mn1);
                float p11 = fast_exp2(sacc[j][3] - mn1);
                s0 += p00 + p01; s1 += p10 + p11;
                uint32_t h00, l00, h01, l01, h10, l10, h11, l11;
                split_tf32(p00, h00, l00); split_tf32(p01, h01, l01);
                split_tf32(p10, h10, l10); split_tf32(p11, h11, l11);
                *(uint2*)&Phi[(r0)     * PSTR + j * 8 + 2 * qid] = make_uint2(h00, h01);
                *(uint2*)&Plo[(r0)     * PSTR + j * 8 + 2 * qid] = make_uint2(l00, l01);
                *(uint2*)&Phi[(r0 + 8) * PSTR + j * 8 + 2 * qid] = make_uint2(h10, h11);
                *(uint2*)&Plo[(r0 + 8) * PSTR + j * 8 + 2 * qid] = make_uint2(l10, l11);
                oacc[j][0] *= c0; oacc[j][1] *= c0;
                oacc[j][2] *= c1; oacc[j][3] *= c1;
            }
            s0 += __shfl_xor_sync(0xffffffff, s0, 1);
            s0 += __shfl_xor_sync(0xffffffff, s0, 2);
            s1 += __shfl_xor_sync(0xffffffff, s1, 1);
            s1 += __shfl_xor_sync(0xffffffff, s1, 2);
            l0 = l0 * c0 + s0;
            l1 = l1 * c1 + s1;
        }
        __syncwarp();

        // ---- O += P @ V (3xTF32) ----
#pragma unroll
        for (int k = 0; k < 8; k++) {
            const int kk = k * 8;
            uint32_t ah[4], al[4];
            ah[0] = Phi[(r0)     * PSTR + kk + qid];     al[0] = Plo[(r0)     * PSTR + kk + qid];
            ah[1] = Phi[(r0 + 8) * PSTR + kk + qid];     al[1] = Plo[(r0 + 8) * PSTR + kk + qid];
            ah[2] = Phi[(r0)     * PSTR + kk + qid + 4]; al[2] = Plo[(r0)     * PSTR + kk + qid + 4];
            ah[3] = Phi[(r0 + 8) * PSTR + kk + qid + 4]; al[3] = Plo[(r0 + 8) * PSTR + kk + qid + 4];
#pragma unroll
            for (int j = 0; j < 8; j++) {
                int n = j * 8 + grp;
                uint32_t bh0 = Vhi[(kk + qid)     * VSTR + n];
                uint32_t bl0 = Vlo[(kk + qid)     * VSTR + n];
                uint32_t bh1 = Vhi[(kk + qid + 4) * VSTR + n];
                uint32_t bl1 = Vlo[(kk + qid + 4) * VSTR + n];
                mma_tf32(oacc[j][0], oacc[j][1], oacc[j][2], oacc[j][3],
                         ah[0], ah[1], ah[2], ah[3], bh0, bh1);
                mma_tf32(oacc[j][0], oacc[j][1], oacc[j][2], oacc[j][3],
                         ah[0], ah[1], ah[2], ah[3], bl0, bl1);
                mma_tf32(oacc[j][0], oacc[j][1], oacc[j][2], oacc[j][3],
                         al[0], al[1], al[2], al[3], bh0, bh1);
            }
        }
        __syncthreads();
    }

    // Epilogue: normalize and write O rows r0, r0+8
    {
        float inv0 = 1.f / l0, inv1 = 1.f / l1;
        float* op0 = g_O + (size_t)(b * Sc + q0blk + r0) * Dc + h * HDc;
        float* op1 = g_O + (size_t)(b * Sc + q0blk + r0 + 8) * Dc + h * HDc;
#pragma unroll
        for (int j = 0; j < 8; j++) {
            *(float2*)&op0[j * 8 + 2 * qid] = make_float2(oacc[j][0] * inv0, oacc[j][1] * inv0);
            *(float2*)&op1[j * 8 + 2 * qid] = make_float2(oacc[j][2] * inv1, oacc[j][3] * inv1);
        }
    }
}

// ---------------------------------------------------------------------------
extern "C" void kernel_launch(void* const* d_in, const int* in_sizes, int n_in,
                              void* d_out, int out_size) {
    const float* X  = (const float*)d_in[0];
    const float* Wq = (const float*)d_in[1];
    const float* Wk = (const float*)d_in[2];
    const float* Wv = (const float*)d_in[3];
    const float* Wo = (const float*)d_in[4];
    float* out = (float*)d_out;

    uint32_t *Qh, *Ql, *Kh, *Kl, *Vh, *Vl;
    float* Ob;
    cudaGetSymbolAddress((void**)&Qh, g_Qhi);
    cudaGetSymbolAddress((void**)&Ql, g_Qlo);
    cudaGetSymbolAddress((void**)&Kh, g_Khi);
    cudaGetSymbolAddress((void**)&Kl, g_Klo);
    cudaGetSymbolAddress((void**)&Vh, g_Vhi);
    cudaGetSymbolAddress((void**)&Vl, g_Vlo);
    cudaGetSymbolAddress((void**)&Ob, g_O);

    cudaFuncSetAttribute(flash_attn_tc2, cudaFuncAttributeMaxDynamicSharedMemorySize, ATT_SMEM);

    const int M = Bc * Sc;  // 4096

    // Projections with pre-split epilogues (Q also folds softmax scale, log2 domain)
    tf32gemm_split<<<dim3(Dc / 128, M / 128), 256>>>(X, Wq, Qh, Ql, SCALE * LOG2E, M, Dc, Dc);
    tf32gemm_split<<<dim3((KVHc * HDc) / 128, M / 128), 256>>>(X, Wk, Kh, Kl, 1.f, M, KVHc * HDc, Dc);
    tf32gemm_split<<<dim3((KVHc * HDc) / 128, M / 128), 256>>>(X, Wv, Vh, Vl, 1.f, M, KVHc * HDc, Dc);

    flash_attn_tc2<<<dim3(Sc / 64, Hc, Bc), 128, ATT_SMEM>>>();

    tf32gemm<<<dim3(Dc / 128, M / 128), 256>>>(Ob, Wo, out, M, Dc, Dc);
}

// round 10
// speedup vs baseline: 2.7072x; 1.0798x over previous
#include <cuda_runtime.h>
#include <cstdint>

// Problem constants
constexpr int Bc  = 2;
constexpr int Sc  = 2048;
constexpr int Dc  = 2048;
constexpr int Hc  = 32;
constexpr int KVHc = 8;
constexpr int HDc = 64;
constexpr float SCALE = 0.125f;   // 1/sqrt(64)
constexpr float LOG2E = 1.4426950408889634f;

// Scratch (allocation-free rule: __device__ globals)
// Q/K/V stored PRE-SPLIT as tf32 (hi, lo) bit patterns by the GEMM epilogues.
__device__ uint32_t g_Qhi[(size_t)Bc * Sc * Dc];
__device__ uint32_t g_Qlo[(size_t)Bc * Sc * Dc];
__device__ uint32_t g_Khi[(size_t)Bc * Sc * KVHc * HDc];
__device__ uint32_t g_Klo[(size_t)Bc * Sc * KVHc * HDc];
__device__ uint32_t g_Vhi[(size_t)Bc * Sc * KVHc * HDc];
__device__ uint32_t g_Vlo[(size_t)Bc * Sc * KVHc * HDc];
__device__ float    g_O  [(size_t)Bc * Sc * Dc];       // tf32-rounded by epilogue
// tf32-rounded copies of the raw inputs (so GEMM hot loops need no cvt)
__device__ float g_Xr [(size_t)Bc * Sc * Dc];
__device__ float g_Wqr[(size_t)Dc * Dc];
__device__ float g_Wkr[(size_t)Dc * KVHc * HDc];
__device__ float g_Wvr[(size_t)Dc * KVHc * HDc];
__device__ float g_Wor[(size_t)Dc * Dc];

// ---------------------------------------------------------------------------
// Common PTX helpers
// ---------------------------------------------------------------------------
__device__ __forceinline__ void cp16(void* smem, const void* gmem) {
    uint32_t s = (uint32_t)__cvta_generic_to_shared(smem);
    asm volatile("cp.async.cg.shared.global [%0], [%1], 16;\n" :: "r"(s), "l"(gmem));
}
__device__ __forceinline__ void cp_commit() { asm volatile("cp.async.commit_group;\n"); }
__device__ __forceinline__ void cp_wait0()  { asm volatile("cp.async.wait_group 0;\n"); }

__device__ __forceinline__ uint32_t to_tf32(float f) {
    uint32_t r;
    asm("cvt.rna.tf32.f32 %0, %1;" : "=r"(r) : "f"(f));
    return r;
}
__device__ __forceinline__ void split_tf32(float v, uint32_t& hi, uint32_t& lo) {
    hi = to_tf32(v);
    lo = to_tf32(v - __uint_as_float(hi));
}

__device__ __forceinline__ void mma_tf32(float& c0, float& c1, float& c2, float& c3,
                                         uint32_t a0, uint32_t a1, uint32_t a2, uint32_t a3,
                                         uint32_t b0, uint32_t b1) {
    asm volatile(
        "mma.sync.aligned.m16n8k8.row.col.f32.tf32.tf32.f32 "
        "{%0,%1,%2,%3}, {%4,%5,%6,%7}, {%8,%9}, {%0,%1,%2,%3};\n"
        : "+f"(c0), "+f"(c1), "+f"(c2), "+f"(c3)
        : "r"(a0), "r"(a1), "r"(a2), "r"(a3), "r"(b0), "r"(b1));
}

// Fast 2^y for y <= 0 (FMA pipe only, no MUFU). Rel err ~4e-5.
__device__ __forceinline__ float fast_exp2(float y) {
    y = fmaxf(y, -80.f);
    float t = y + 12582912.f;
    int k = __float_as_int(t) - 0x4B400000;
    float f = y - (t - 12582912.f);
    float r = fmaf(f, 0.0096181291f, 0.0555041087f);
    r = fmaf(f, r, 0.2402265069f);
    r = fmaf(f, r, 0.6931471806f);
    r = fmaf(f, r, 1.0f);
    return __int_as_float(__float_as_int(r) + (k << 23));
}

// ---------------------------------------------------------------------------
// Elementwise tf32 rounding pre-pass (n multiple of 1024)
// ---------------------------------------------------------------------------
__global__ __launch_bounds__(256) void round_tf32(const float* __restrict__ in,
                                                  float* __restrict__ out, size_t n) {
    size_t i = ((size_t)blockIdx.x * 256 + threadIdx.x) * 4;
    if (i >= n) return;
    float4 v = *(const float4*)(in + i);
    v.x = __uint_as_float(to_tf32(v.x));
    v.y = __uint_as_float(to_tf32(v.y));
    v.z = __uint_as_float(to_tf32(v.z));
    v.w = __uint_as_float(to_tf32(v.w));
    *(float4*)(out + i) = v;
}

// ---------------------------------------------------------------------------
// TF32 GEMM core (128x128 tile, BK=16, 8 warps, m16n8k8).
// Inputs MUST be pre-rounded to tf32 -> no cvt in the hot loop.
// ---------------------------------------------------------------------------
constexpr int ASTRIDE = 20;
constexpr int BSTRIDE = 136;
constexpr int ABUF = 128 * ASTRIDE;
constexpr int BBUF = 16 * BSTRIDE;

#define GEMM_BODY                                                                   \
    __shared__ float As[2][ABUF];                                                   \
    __shared__ float Bs[2][BBUF];                                                   \
    const int tid  = threadIdx.x;                                                   \
    const int warp = tid >> 5;                                                      \
    const int lane = tid & 31;                                                      \
    const int grp  = lane >> 2;                                                     \
    const int qid  = lane & 3;                                                      \
    const int warpM = warp >> 2;                                                    \
    const int warpN = warp & 3;                                                     \
    const int bx = blockIdx.x;                                                      \
    const int by = blockIdx.y;                                                      \
    const int numTiles = K / 16;                                                    \
    auto load_tile = [&](int t, int s) {                                            \
        int k0 = t * 16;                                                            \
        {                                                                           \
            int r = tid >> 2, cc = tid & 3;                                         \
            cp16(&As[s][r * ASTRIDE + cc * 4],                                      \
                 A + (size_t)(by * 128 + r) * K + k0 + cc * 4);                     \
            r = (tid + 256) >> 2; cc = (tid + 256) & 3;                             \
            cp16(&As[s][r * ASTRIDE + cc * 4],                                      \
                 A + (size_t)(by * 128 + r) * K + k0 + cc * 4);                     \
        }                                                                           \
        {                                                                           \
            int r = tid >> 5, cc = tid & 31;                                        \
            cp16(&Bs[s][r * BSTRIDE + cc * 4],                                      \
                 Bm + (size_t)(k0 + r) * N + bx * 128 + cc * 4);                    \
            r = (tid + 256) >> 5; cc = (tid + 256) & 31;                            \
            cp16(&Bs[s][r * BSTRIDE + cc * 4],                                      \
                 Bm + (size_t)(k0 + r) * N + bx * 128 + cc * 4);                    \
        }                                                                           \
        cp_commit();                                                                \
    };                                                                              \
    float acc[4][4][4];                                                             \
    _Pragma("unroll")                                                               \
    for (int i = 0; i < 4; i++)                                                     \
        _Pragma("unroll")                                                           \
        for (int j = 0; j < 4; j++)                                                 \
            _Pragma("unroll")                                                       \
            for (int r = 0; r < 4; r++) acc[i][j][r] = 0.f;                         \
    load_tile(0, 0);                                                                \
    for (int t = 0; t < numTiles; t++) {                                            \
        cp_wait0();                                                                 \
        __syncthreads();                                                            \
        if (t + 1 < numTiles) load_tile(t + 1, (t + 1) & 1);                        \
        const uint32_t* Asb = (const uint32_t*)As[t & 1];                           \
        const uint32_t* Bsb = (const uint32_t*)Bs[t & 1];                           \
        _Pragma("unroll")                                                           \
        for (int kk = 0; kk < 16; kk += 8) {                                        \
            uint32_t af[4][4];                                                      \
            _Pragma("unroll")                                                       \
            for (int i = 0; i < 4; i++) {                                           \
                int mr = warpM * 64 + i * 16 + grp;                                 \
                af[i][0] = Asb[(mr)     * ASTRIDE + kk + qid];                      \
                af[i][1] = Asb[(mr + 8) * ASTRIDE + kk + qid];                      \
                af[i][2] = Asb[(mr)     * ASTRIDE + kk + qid + 4];                  \
                af[i][3] = Asb[(mr + 8) * ASTRIDE + kk + qid + 4];                  \
            }                                                                       \
            uint32_t bf[4][2];                                                      \
            _Pragma("unroll")                                                       \
            for (int j = 0; j < 4; j++) {                                           \
                int nc = warpN * 32 + j * 8 + grp;                                  \
                bf[j][0] = Bsb[(kk + qid)     * BSTRIDE + nc];                      \
                bf[j][1] = Bsb[(kk + qid + 4) * BSTRIDE + nc];                      \
            }                                                                       \
            _Pragma("unroll")                                                       \
            for (int i = 0; i < 4; i++)                                             \
                _Pragma("unroll")                                                   \
                for (int j = 0; j < 4; j++)                                         \
                    mma_tf32(acc[i][j][0], acc[i][j][1], acc[i][j][2], acc[i][j][3],\
                             af[i][0], af[i][1], af[i][2], af[i][3],                \
                             bf[j][0], bf[j][1]);                                   \
        }                                                                           \
        __syncthreads();                                                            \
    }

__global__ __launch_bounds__(256) void tf32gemm(const float* __restrict__ A,
                                                const float* __restrict__ Bm,
                                                float* __restrict__ C,
                                                int M, int N, int K) {
    GEMM_BODY
#pragma unroll
    for (int i = 0; i < 4; i++) {
        int mr = by * 128 + warpM * 64 + i * 16 + grp;
#pragma unroll
        for (int j = 0; j < 4; j++) {
            int nc = bx * 128 + warpN * 32 + j * 8 + 2 * qid;
            *(float2*)&C[(size_t)mr * N + nc]       = make_float2(acc[i][j][0], acc[i][j][1]);
            *(float2*)&C[(size_t)(mr + 8) * N + nc] = make_float2(acc[i][j][2], acc[i][j][3]);
        }
    }
}

__global__ __launch_bounds__(256) void tf32gemm_split(const float* __restrict__ A,
                                                      const float* __restrict__ Bm,
                                                      uint32_t* __restrict__ Chi,
                                                      uint32_t* __restrict__ Clo,
                                                      float prescale,
                                                      int M, int N, int K) {
    GEMM_BODY
#pragma unroll
    for (int i = 0; i < 4; i++) {
        int mr = by * 128 + warpM * 64 + i * 16 + grp;
#pragma unroll
        for (int j = 0; j < 4; j++) {
            int nc = bx * 128 + warpN * 32 + j * 8 + 2 * qid;
            uint32_t h[4], l[4];
#pragma unroll
            for (int r = 0; r < 4; r++) split_tf32(acc[i][j][r] * prescale, h[r], l[r]);
            *(uint2*)&Chi[(size_t)mr * N + nc]       = make_uint2(h[0], h[1]);
            *(uint2*)&Clo[(size_t)mr * N + nc]       = make_uint2(l[0], l[1]);
            *(uint2*)&Chi[(size_t)(mr + 8) * N + nc] = make_uint2(h[2], h[3]);
            *(uint2*)&Clo[(size_t)(mr + 8) * N + nc] = make_uint2(l[2], l[3]);
        }
    }
}

// ---------------------------------------------------------------------------
// Tensor-core flash attention.
// S = QK^T: 3xTF32 (pre-split operands). PV: 2-pass (Phi*Vhi + Phi*Vlo).
// K(t+1) prefetched during softmax+PV; V(t+1) after PV.
// CTA: 64 queries x 1 head, 128 threads (4 warps).
// ---------------------------------------------------------------------------
constexpr int KSTR = 68;
constexpr int VSTR = 72;
constexpr int PSTR = 68;
constexpr int ATT_SMEM = (2 * 64 * KSTR + 2 * 64 * VSTR + 64 * PSTR) * 4;  // 89088 B

__global__ __launch_bounds__(128) void flash_attn_tc3() {
    extern __shared__ uint32_t smu[];
    uint32_t* Khi = smu;
    uint32_t* Klo = Khi + 64 * KSTR;
    uint32_t* Vhi = Klo + 64 * KSTR;
    uint32_t* Vlo = Vhi + 64 * VSTR;
    uint32_t* Phi = Vlo + 64 * VSTR;

    const int tid  = threadIdx.x;
    const int warp = tid >> 5;
    const int lane = tid & 31;
    const int grp  = lane >> 2;
    const int qid  = lane & 3;
    const int h = blockIdx.y, b = blockIdx.z;
    const int g = h >> 2;
    const int q0blk = blockIdx.x * 64;

    const int r0 = warp * 16 + grp;

    auto stageK = [&](int t) {
#pragma unroll
        for (int i = 0; i < 8; i++) {
            int c = tid + i * 128;
            int row = c >> 4, cc = (c & 15) * 4;
            size_t gb = (size_t)(b * Sc + t * 64 + row) * (KVHc * HDc) + g * HDc + cc;
            cp16(&Khi[row * KSTR + cc], g_Khi + gb);
            cp16(&Klo[row * KSTR + cc], g_Klo + gb);
        }
        cp_commit();
    };
    auto stageV = [&](int t) {
#pragma unroll
        for (int i = 0; i < 8; i++) {
            int c = tid + i * 128;
            int row = c >> 4, cc = (c & 15) * 4;
            size_t gb = (size_t)(b * Sc + t * 64 + row) * (KVHc * HDc) + g * HDc + cc;
            cp16(&Vhi[row * VSTR + cc], g_Vhi + gb);
            cp16(&Vlo[row * VSTR + cc], g_Vlo + gb);
        }
        cp_commit();
    };

    // Q fragments (pre-scaled, pre-split) -> registers, loop-invariant
    uint32_t qh[8][4], ql[8][4];
    {
        const size_t base = (size_t)(b * Sc + q0blk + r0) * Dc + h * HDc;
        const size_t row8 = (size_t)8 * Dc;
#pragma unroll
        for (int k = 0; k < 8; k++) {
            int c0 = k * 8 + qid;
            qh[k][0] = g_Qhi[base + c0];            ql[k][0] = g_Qlo[base + c0];
            qh[k][1] = g_Qhi[base + row8 + c0];     ql[k][1] = g_Qlo[base + row8 + c0];
            qh[k][2] = g_Qhi[base + c0 + 4];        ql[k][2] = g_Qlo[base + c0 + 4];
            qh[k][3] = g_Qhi[base + row8 + c0 + 4]; ql[k][3] = g_Qlo[base + row8 + c0 + 4];
        }
    }

    float oacc[8][4];
#pragma unroll
    for (int j = 0; j < 8; j++)
#pragma unroll
        for (int r = 0; r < 4; r++) oacc[j][r] = 0.f;
    float m0 = -1e30f, m1 = -1e30f, l0 = 0.f, l1 = 0.f;

    stageK(0);
    stageV(0);

    for (int t = 0; t < 32; t++) {
        cp_wait0();
        __syncthreads();

        // ---- S = Q @ K^T (3xTF32) ----
        float sacc[8][4];
#pragma unroll
        for (int j = 0; j < 8; j++)
#pragma unroll
            for (int r = 0; r < 4; r++) sacc[j][r] = 0.f;

#pragma unroll
        for (int k = 0; k < 8; k++) {
            const int kk = k * 8;
#pragma unroll
            for (int j = 0; j < 8; j++) {
                int n = j * 8 + grp;
                uint32_t bh0 = Khi[n * KSTR + kk + qid];
                uint32_t bl0 = Klo[n * KSTR + kk + qid];
                uint32_t bh1 = Khi[n * KSTR + kk + qid + 4];
                uint32_t bl1 = Klo[n * KSTR + kk + qid + 4];
                mma_tf32(sacc[j][0], sacc[j][1], sacc[j][2], sacc[j][3],
                         qh[k][0], qh[k][1], qh[k][2], qh[k][3], bh0, bh1);
                mma_tf32(sacc[j][0], sacc[j][1], sacc[j][2], sacc[j][3],
                         qh[k][0], qh[k][1], qh[k][2], qh[k][3], bl0, bl1);
                mma_tf32(sacc[j][0], sacc[j][1], sacc[j][2], sacc[j][3],
                         ql[k][0], ql[k][1], ql[k][2], ql[k][3], bh0, bh1);
            }
        }
        __syncthreads();                 // all warps done reading K tile
        if (t + 1 < 32) stageK(t + 1);   // K prefetch hides behind softmax+PV

        // ---- online softmax (log2 domain); P (tf32 hi only) -> Phi ----
        {
            float mx0 = -1e30f, mx1 = -1e30f;
#pragma unroll
            for (int j = 0; j < 8; j++) {
                mx0 = fmaxf(mx0, fmaxf(sacc[j][0], sacc[j][1]));
                mx1 = fmaxf(mx1, fmaxf(sacc[j][2], sacc[j][3]));
            }
            mx0 = fmaxf(mx0, __shfl_xor_sync(0xffffffff, mx0, 1));
            mx0 = fmaxf(mx0, __shfl_xor_sync(0xffffffff, mx0, 2));
            mx1 = fmaxf(mx1, __shfl_xor_sync(0xffffffff, mx1, 1));
            mx1 = fmaxf(mx1, __shfl_xor_sync(0xffffffff, mx1, 2));

            float mn0 = fmaxf(m0, mx0), mn1 = fmaxf(m1, mx1);
            float c0 = fast_exp2(m0 - mn0), c1 = fast_exp2(m1 - mn1);
            m0 = mn0; m1 = mn1;

            float s0 = 0.f, s1 = 0.f;
#pragma unroll
            for (int j = 0; j < 8; j++) {
                float p00 = fast_exp2(sacc[j][0] - mn0);
                float p01 = fast_exp2(sacc[j][1] - mn0);
                float p10 = fast_exp2(sacc[j][2] - mn1);
                float p11 = fast_exp2(sacc[j][3] - mn1);
                s0 += p00 + p01; s1 += p10 + p11;
                *(uint2*)&Phi[(r0)     * PSTR + j * 8 + 2 * qid] =
                    make_uint2(to_tf32(p00), to_tf32(p01));
                *(uint2*)&Phi[(r0 + 8) * PSTR + j * 8 + 2 * qid] =
                    make_uint2(to_tf32(p10), to_tf32(p11));
                oacc[j][0] *= c0; oacc[j][1] *= c0;
                oacc[j][2] *= c1; oacc[j][3] *= c1;
            }
            s0 += __shfl_xor_sync(0xffffffff, s0, 1);
            s0 += __shfl_xor_sync(0xffffffff, s0, 2);
            s1 += __shfl_xor_sync(0xffffffff, s1, 1);
            s1 += __shfl_xor_sync(0xffffffff, s1, 2);
            l0 = l0 * c0 + s0;
            l1 = l1 * c1 + s1;
        }
        __syncwarp();

        // ---- O += P @ V (2-pass: Phi*Vhi + Phi*Vlo) ----
#pragma unroll
        for (int k = 0; k < 8; k++) {
            const int kk = k * 8;
            uint32_t ah[4];
            ah[0] = Phi[(r0)     * PSTR + kk + qid];
            ah[1] = Phi[(r0 + 8) * PSTR + kk + qid];
            ah[2] = Phi[(r0)     * PSTR + kk + qid + 4];
            ah[3] = Phi[(r0 + 8) * PSTR + kk + qid + 4];
#pragma unroll
            for (int j = 0; j < 8; j++) {
                int n = j * 8 + grp;
                uint32_t bh0 = Vhi[(kk + qid)     * VSTR + n];
                uint32_t bl0 = Vlo[(kk + qid)     * VSTR + n];
                uint32_t bh1 = Vhi[(kk + qid + 4) * VSTR + n];
                uint32_t bl1 = Vlo[(kk + qid + 4) * VSTR + n];
                mma_tf32(oacc[j][0], oacc[j][1], oacc[j][2], oacc[j][3],
                         ah[0], ah[1], ah[2], ah[3], bh0, bh1);
                mma_tf32(oacc[j][0], oacc[j][1], oacc[j][2], oacc[j][3],
                         ah[0], ah[1], ah[2], ah[3], bl0, bl1);
            }
        }
        __syncthreads();                 // all warps done reading V tile
        if (t + 1 < 32) stageV(t + 1);
    }

    // Epilogue: normalize, round to tf32 (so the out-proj GEMM needs no cvt)
    {
        float inv0 = 1.f / l0, inv1 = 1.f / l1;
        float* op0 = g_O + (size_t)(b * Sc + q0blk + r0) * Dc + h * HDc;
        float* op1 = g_O + (size_t)(b * Sc + q0blk + r0 + 8) * Dc + h * HDc;
#pragma unroll
        for (int j = 0; j < 8; j++) {
            *(float2*)&op0[j * 8 + 2 * qid] = make_float2(
                __uint_as_float(to_tf32(oacc[j][0] * inv0)),
                __uint_as_float(to_tf32(oacc[j][1] * inv0)));
            *(float2*)&op1[j * 8 + 2 * qid] = make_float2(
                __uint_as_float(to_tf32(oacc[j][2] * inv1)),
                __uint_as_float(to_tf32(oacc[j][3] * inv1)));
        }
    }
}

// ---------------------------------------------------------------------------
extern "C" void kernel_launch(void* const* d_in, const int* in_sizes, int n_in,
                              void* d_out, int out_size) {
    const float* X  = (const float*)d_in[0];
    const float* Wq = (const float*)d_in[1];
    const float* Wk = (const float*)d_in[2];
    const float* Wv = (const float*)d_in[3];
    const float* Wo = (const float*)d_in[4];
    float* out = (float*)d_out;

    uint32_t *Qh, *Ql, *Kh, *Kl, *Vh, *Vl;
    float *Ob, *Xr, *Wqr, *Wkr, *Wvr, *Wor;
    cudaGetSymbolAddress((void**)&Qh, g_Qhi);
    cudaGetSymbolAddress((void**)&Ql, g_Qlo);
    cudaGetSymbolAddress((void**)&Kh, g_Khi);
    cudaGetSymbolAddress((void**)&Kl, g_Klo);
    cudaGetSymbolAddress((void**)&Vh, g_Vhi);
    cudaGetSymbolAddress((void**)&Vl, g_Vlo);
    cudaGetSymbolAddress((void**)&Ob, g_O);
    cudaGetSymbolAddress((void**)&Xr, g_Xr);
    cudaGetSymbolAddress((void**)&Wqr, g_Wqr);
    cudaGetSymbolAddress((void**)&Wkr, g_Wkr);
    cudaGetSymbolAddress((void**)&Wvr, g_Wvr);
    cudaGetSymbolAddress((void**)&Wor, g_Wor);

    cudaFuncSetAttribute(flash_attn_tc3, cudaFuncAttributeMaxDynamicSharedMemorySize, ATT_SMEM);

    const int M = Bc * Sc;         // 4096
    const size_t nX = (size_t)M * Dc;
    const size_t nWq = (size_t)Dc * Dc;
    const size_t nWk = (size_t)Dc * KVHc * HDc;

    // tf32 pre-rounding pass (moves cvt.rna out of all GEMM hot loops)
    round_tf32<<<(int)(nX  / 1024), 256>>>(X,  Xr,  nX);
    round_tf32<<<(int)(nWq / 1024), 256>>>(Wq, Wqr, nWq);
    round_tf32<<<(int)(nWk / 1024), 256>>>(Wk, Wkr, nWk);
    round_tf32<<<(int)(nWk / 1024), 256>>>(Wv, Wvr, nWk);
    round_tf32<<<(int)(nWq / 1024), 256>>>(Wo, Wor, nWq);

    // Projections with pre-split epilogues (Q folds softmax scale, log2 domain)
    tf32gemm_split<<<dim3(Dc / 128, M / 128), 256>>>(Xr, Wqr, Qh, Ql, SCALE * LOG2E, M, Dc, Dc);
    tf32gemm_split<<<dim3((KVHc * HDc) / 128, M / 128), 256>>>(Xr, Wkr, Kh, Kl, 1.f, M, KVHc * HDc, Dc);
    tf32gemm_split<<<dim3((KVHc * HDc) / 128, M / 128), 256>>>(Xr, Wvr, Vh, Vl, 1.f, M, KVHc * HDc, Dc);

    flash_attn_tc3<<<dim3(Sc / 64, Hc, Bc), 128, ATT_SMEM>>>();

    tf32gemm<<<dim3(Dc / 128, M / 128), 256>>>(Ob, Wor, out, M, Dc, Dc);
}

// round 11
// speedup vs baseline: 2.9325x; 1.0832x over previous
#include <cuda_runtime.h>
#include <cstdint>

// Problem constants
constexpr int Bc  = 2;
constexpr int Sc  = 2048;
constexpr int Dc  = 2048;
constexpr int Hc  = 32;
constexpr int KVHc = 8;
constexpr int HDc = 64;
constexpr float SCALE = 0.125f;   // 1/sqrt(64)
constexpr float LOG2E = 1.4426950408889634f;

// Scratch (allocation-free rule: __device__ globals)
__device__ uint32_t g_Qhi[(size_t)Bc * Sc * Dc];                // Q tf32 bits (prescaled)
__device__ uint2    g_Khl[(size_t)Bc * Sc * KVHc * HDc];        // K (hi,lo) interleaved
__device__ uint2    g_Vhl[(size_t)Bc * Sc * KVHc * HDc];        // V (hi,lo) interleaved
__device__ float    g_O  [(size_t)Bc * Sc * Dc];                // tf32-rounded by epilogue
// tf32-rounded copies of raw inputs (GEMM hot loops need no cvt)
__device__ float g_Xr [(size_t)Bc * Sc * Dc];
__device__ float g_Wqr[(size_t)Dc * Dc];
__device__ float g_Wkr[(size_t)Dc * KVHc * HDc];
__device__ float g_Wvr[(size_t)Dc * KVHc * HDc];
__device__ float g_Wor[(size_t)Dc * Dc];

// ---------------------------------------------------------------------------
// Common PTX helpers
// ---------------------------------------------------------------------------
__device__ __forceinline__ void cp16(void* smem, const void* gmem) {
    uint32_t s = (uint32_t)__cvta_generic_to_shared(smem);
    asm volatile("cp.async.cg.shared.global [%0], [%1], 16;\n" :: "r"(s), "l"(gmem));
}
__device__ __forceinline__ void cp_commit() { asm volatile("cp.async.commit_group;\n"); }
__device__ __forceinline__ void cp_wait0()  { asm volatile("cp.async.wait_group 0;\n"); }
__device__ __forceinline__ void cp_wait1()  { asm volatile("cp.async.wait_group 1;\n"); }

__device__ __forceinline__ uint32_t to_tf32(float f) {
    uint32_t r;
    asm("cvt.rna.tf32.f32 %0, %1;" : "=r"(r) : "f"(f));
    return r;
}
__device__ __forceinline__ void split_tf32(float v, uint32_t& hi, uint32_t& lo) {
    hi = to_tf32(v);
    lo = to_tf32(v - __uint_as_float(hi));
}

__device__ __forceinline__ void mma_tf32(float& c0, float& c1, float& c2, float& c3,
                                         uint32_t a0, uint32_t a1, uint32_t a2, uint32_t a3,
                                         uint32_t b0, uint32_t b1) {
    asm volatile(
        "mma.sync.aligned.m16n8k8.row.col.f32.tf32.tf32.f32 "
        "{%0,%1,%2,%3}, {%4,%5,%6,%7}, {%8,%9}, {%0,%1,%2,%3};\n"
        : "+f"(c0), "+f"(c1), "+f"(c2), "+f"(c3)
        : "r"(a0), "r"(a1), "r"(a2), "r"(a3), "r"(b0), "r"(b1));
}

// Fast 2^y for y <= 0 (FMA pipe only, no MUFU). Rel err ~4e-5.
__device__ __forceinline__ float fast_exp2(float y) {
    y = fmaxf(y, -80.f);
    float t = y + 12582912.f;
    int k = __float_as_int(t) - 0x4B400000;
    float f = y - (t - 12582912.f);
    float r = fmaf(f, 0.0096181291f, 0.0555041087f);
    r = fmaf(f, r, 0.2402265069f);
    r = fmaf(f, r, 0.6931471806f);
    r = fmaf(f, r, 1.0f);
    return __int_as_float(__float_as_int(r) + (k << 23));
}

// ---------------------------------------------------------------------------
// Elementwise tf32 rounding pre-pass (n multiple of 1024)
// ---------------------------------------------------------------------------
__global__ __launch_bounds__(256) void round_tf32(const float* __restrict__ in,
                                                  float* __restrict__ out, size_t n) {
    size_t i = ((size_t)blockIdx.x * 256 + threadIdx.x) * 4;
    if (i >= n) return;
    float4 v = *(const float4*)(in + i);
    v.x = __uint_as_float(to_tf32(v.x));
    v.y = __uint_as_float(to_tf32(v.y));
    v.z = __uint_as_float(to_tf32(v.z));
    v.w = __uint_as_float(to_tf32(v.w));
    *(float4*)(out + i) = v;
}

// ---------------------------------------------------------------------------
// TF32 GEMM core (128x128 tile, BK=16, 8 warps, m16n8k8).
// Inputs MUST be pre-rounded to tf32 -> no cvt in the hot loop.
// ---------------------------------------------------------------------------
constexpr int ASTRIDE = 20;
constexpr int BSTRIDE = 136;
constexpr int ABUF = 128 * ASTRIDE;
constexpr int BBUF = 16 * BSTRIDE;

#define GEMM_BODY                                                                   \
    __shared__ float As[2][ABUF];                                                   \
    __shared__ float Bs[2][BBUF];                                                   \
    const int tid  = threadIdx.x;                                                   \
    const int warp = tid >> 5;                                                      \
    const int lane = tid & 31;                                                      \
    const int grp  = lane >> 2;                                                     \
    const int qid  = lane & 3;                                                      \
    const int warpM = warp >> 2;                                                    \
    const int warpN = warp & 3;                                                     \
    const int bx = blockIdx.x;                                                      \
    const int by = blockIdx.y;                                                      \
    const int numTiles = K / 16;                                                    \
    auto load_tile = [&](int t, int s) {                                            \
        int k0 = t * 16;                                                            \
        {                                                                           \
            int r = tid >> 2, cc = tid & 3;                                         \
            cp16(&As[s][r * ASTRIDE + cc * 4],                                      \
                 A + (size_t)(by * 128 + r) * K + k0 + cc * 4);                     \
            r = (tid + 256) >> 2; cc = (tid + 256) & 3;                             \
            cp16(&As[s][r * ASTRIDE + cc * 4],                                      \
                 A + (size_t)(by * 128 + r) * K + k0 + cc * 4);                     \
        }                                                                           \
        {                                                                           \
            int r = tid >> 5, cc = tid & 31;                                        \
            cp16(&Bs[s][r * BSTRIDE + cc * 4],                                      \
                 Bm + (size_t)(k0 + r) * N + bx * 128 + cc * 4);                    \
            r = (tid + 256) >> 5; cc = (tid + 256) & 31;                            \
            cp16(&Bs[s][r * BSTRIDE + cc * 4],                                      \
                 Bm + (size_t)(k0 + r) * N + bx * 128 + cc * 4);                    \
        }                                                                           \
        cp_commit();                                                                \
    };                                                                              \
    float acc[4][4][4];                                                             \
    _Pragma("unroll")                                                               \
    for (int i = 0; i < 4; i++)                                                     \
        _Pragma("unroll")                                                           \
        for (int j = 0; j < 4; j++)                                                 \
            _Pragma("unroll")                                                       \
            for (int r = 0; r < 4; r++) acc[i][j][r] = 0.f;                         \
    load_tile(0, 0);                                                                \
    for (int t = 0; t < numTiles; t++) {                                            \
        cp_wait0();                                                                 \
        __syncthreads();                                                            \
        if (t + 1 < numTiles) load_tile(t + 1, (t + 1) & 1);                        \
        const uint32_t* Asb = (const uint32_t*)As[t & 1];                           \
        const uint32_t* Bsb = (const uint32_t*)Bs[t & 1];                           \
        _Pragma("unroll")                                                           \
        for (int kk = 0; kk < 16; kk += 8) {                                        \
            uint32_t af[4][4];                                                      \
            _Pragma("unroll")                                                       \
            for (int i = 0; i < 4; i++) {                                           \
                int mr = warpM * 64 + i * 16 + grp;                                 \
                af[i][0] = Asb[(mr)     * ASTRIDE + kk + qid];                      \
                af[i][1] = Asb[(mr + 8) * ASTRIDE + kk + qid];                      \
                af[i][2] = Asb[(mr)     * ASTRIDE + kk + qid + 4];                  \
                af[i][3] = Asb[(mr + 8) * ASTRIDE + kk + qid + 4];                  \
            }                                                                       \
            uint32_t bf[4][2];                                                      \
            _Pragma("unroll")                                                       \
            for (int j = 0; j < 4; j++) {                                           \
                int nc = warpN * 32 + j * 8 + grp;                                  \
                bf[j][0] = Bsb[(kk + qid)     * BSTRIDE + nc];                      \
                bf[j][1] = Bsb[(kk + qid + 4) * BSTRIDE + nc];                      \
            }                                                                       \
            _Pragma("unroll")                                                       \
            for (int i = 0; i < 4; i++)                                             \
                _Pragma("unroll")                                                   \
                for (int j = 0; j < 4; j++)                                         \
                    mma_tf32(acc[i][j][0], acc[i][j][1], acc[i][j][2], acc[i][j][3],\
                             af[i][0], af[i][1], af[i][2], af[i][3],                \
                             bf[j][0], bf[j][1]);                                   \
        }                                                                           \
        __syncthreads();                                                            \
    }

__global__ __launch_bounds__(256) void tf32gemm(const float* __restrict__ A,
                                                const float* __restrict__ Bm,
                                                float* __restrict__ C,
                                                int M, int N, int K) {
    GEMM_BODY
#pragma unroll
    for (int i = 0; i < 4; i++) {
        int mr = by * 128 + warpM * 64 + i * 16 + grp;
#pragma unroll
        for (int j = 0; j < 4; j++) {
            int nc = bx * 128 + warpN * 32 + j * 8 + 2 * qid;
            *(float2*)&C[(size_t)mr * N + nc]       = make_float2(acc[i][j][0], acc[i][j][1]);
            *(float2*)&C[(size_t)(mr + 8) * N + nc] = make_float2(acc[i][j][2], acc[i][j][3]);
        }
    }
}

// Q epilogue: tf32 hi bits only, prescaled
__global__ __launch_bounds__(256) void tf32gemm_hi(const float* __restrict__ A,
                                                   const float* __restrict__ Bm,
                                                   uint32_t* __restrict__ Chi,
                                                   float prescale,
                                                   int M, int N, int K) {
    GEMM_BODY
#pragma unroll
    for (int i = 0; i < 4; i++) {
        int mr = by * 128 + warpM * 64 + i * 16 + grp;
#pragma unroll
        for (int j = 0; j < 4; j++) {
            int nc = bx * 128 + warpN * 32 + j * 8 + 2 * qid;
            *(uint2*)&Chi[(size_t)mr * N + nc] =
                make_uint2(to_tf32(acc[i][j][0] * prescale), to_tf32(acc[i][j][1] * prescale));
            *(uint2*)&Chi[(size_t)(mr + 8) * N + nc] =
                make_uint2(to_tf32(acc[i][j][2] * prescale), to_tf32(acc[i][j][3] * prescale));
        }
    }
}

// K/V epilogue: (hi,lo) interleaved uint2 per element
__global__ __launch_bounds__(256) void tf32gemm_hl(const float* __restrict__ A,
                                                   const float* __restrict__ Bm,
                                                   uint2* __restrict__ Chl,
                                                   int M, int N, int K) {
    GEMM_BODY
#pragma unroll
    for (int i = 0; i < 4; i++) {
        int mr = by * 128 + warpM * 64 + i * 16 + grp;
#pragma unroll
        for (int j = 0; j < 4; j++) {
            int nc = bx * 128 + warpN * 32 + j * 8 + 2 * qid;
            uint32_t h[4], l[4];
#pragma unroll
            for (int r = 0; r < 4; r++) split_tf32(acc[i][j][r], h[r], l[r]);
            *(uint4*)&Chl[(size_t)mr * N + nc]       = make_uint4(h[0], l[0], h[1], l[1]);
            *(uint4*)&Chl[(size_t)(mr + 8) * N + nc] = make_uint4(h[2], l[2], h[3], l[3]);
        }
    }
}

// ---------------------------------------------------------------------------
// Tensor-core flash attention.
// QK: 2-pass (Qhi x Khi + Qhi x Klo), K (hi,lo) interleaved -> LDS.64 frags.
// PV: 2-pass (Phi x Vhi + Phi x Vlo), V interleaved likewise.
// K(t+1) prefetched during softmax+PV; V(t+1) after PV; split wait_groups.
// CTA: 64 queries x 1 head, 128 threads (4 warps).
// ---------------------------------------------------------------------------
constexpr int KSTR2 = 68;   // uint2 stride per K row
constexpr int VSTR2 = 68;   // uint2 stride per V row
constexpr int PSTR  = 72;   // u32 stride per P row
constexpr int ATT_SMEM = (64 * KSTR2 * 8) + (64 * VSTR2 * 8) + (64 * PSTR * 4);  // 88064 B

__global__ __launch_bounds__(128) void flash_attn_tc4() {
    extern __shared__ uint32_t smu[];
    uint2*    Kp  = (uint2*)smu;
    uint2*    Vp  = Kp + 64 * KSTR2;
    uint32_t* Phi = (uint32_t*)(Vp + 64 * VSTR2);

    const int tid  = threadIdx.x;
    const int warp = tid >> 5;
    const int lane = tid & 31;
    const int grp  = lane >> 2;
    const int qid  = lane & 3;
    const int h = blockIdx.y, b = blockIdx.z;
    const int g = h >> 2;
    const int q0blk = blockIdx.x * 64;

    const int r0 = warp * 16 + grp;

    auto stageK = [&](int t) {
#pragma unroll
        for (int i = 0; i < 16; i++) {
            int c = tid + i * 128;            // 0..2047 chunks of 16B
            int row = c >> 5, cc = (c & 31) * 2;   // 32 chunks/row, uint2 offset
            size_t gb = (size_t)(b * Sc + t * 64 + row) * (KVHc * HDc) + g * HDc + cc;
            cp16(&Kp[row * KSTR2 + cc], g_Khl + gb);
        }
        cp_commit();
    };
    auto stageV = [&](int t) {
#pragma unroll
        for (int i = 0; i < 16; i++) {
            int c = tid + i * 128;
            int row = c >> 5, cc = (c & 31) * 2;
            size_t gb = (size_t)(b * Sc + t * 64 + row) * (KVHc * HDc) + g * HDc + cc;
            cp16(&Vp[row * VSTR2 + cc], g_Vhl + gb);
        }
        cp_commit();
    };

    // Q fragments (prescaled tf32 hi) -> registers, loop-invariant
    uint32_t qh[8][4];
    {
        const size_t base = (size_t)(b * Sc + q0blk + r0) * Dc + h * HDc;
        const size_t row8 = (size_t)8 * Dc;
#pragma unroll
        for (int k = 0; k < 8; k++) {
            int c0 = k * 8 + qid;
            qh[k][0] = g_Qhi[base + c0];
            qh[k][1] = g_Qhi[base + row8 + c0];
            qh[k][2] = g_Qhi[base + c0 + 4];
            qh[k][3] = g_Qhi[base + row8 + c0 + 4];
        }
    }

    float oacc[8][4];
#pragma unroll
    for (int j = 0; j < 8; j++)
#pragma unroll
        for (int r = 0; r < 4; r++) oacc[j][r] = 0.f;
    float m0 = -1e30f, m1 = -1e30f, l0 = 0.f, l1 = 0.f;

    stageK(0);
    stageV(0);

    for (int t = 0; t < 32; t++) {
        cp_wait1();          // K(t) ready (V(t) may still be in flight)
        __syncthreads();

        // ---- S = Q @ K^T (2-pass: Qhi*Khi + Qhi*Klo) ----
        float sacc[8][4];
#pragma unroll
        for (int j = 0; j < 8; j++)
#pragma unroll
            for (int r = 0; r < 4; r++) sacc[j][r] = 0.f;

#pragma unroll
        for (int k = 0; k < 8; k++) {
            const int kk = k * 8;
#pragma unroll
            for (int j = 0; j < 8; j++) {
                int n = j * 8 + grp;
                uint2 b0 = Kp[n * KSTR2 + kk + qid];       // (hi, lo) col kk+qid
                uint2 b1 = Kp[n * KSTR2 + kk + qid + 4];   // (hi, lo) col kk+qid+4
                mma_tf32(sacc[j][0], sacc[j][1], sacc[j][2], sacc[j][3],
                         qh[k][0], qh[k][1], qh[k][2], qh[k][3], b0.x, b1.x);
                mma_tf32(sacc[j][0], sacc[j][1], sacc[j][2], sacc[j][3],
                         qh[k][0], qh[k][1], qh[k][2], qh[k][3], b0.y, b1.y);
            }
        }
        __syncthreads();                 // all warps done reading K tile
        if (t + 1 < 32) stageK(t + 1);   // K prefetch hides behind softmax+PV

        // ---- online softmax (log2 domain); P (tf32 hi) -> Phi ----
        {
            float mx0 = -1e30f, mx1 = -1e30f;
#pragma unroll
            for (int j = 0; j < 8; j++) {
                mx0 = fmaxf(mx0, fmaxf(sacc[j][0], sacc[j][1]));
                mx1 = fmaxf(mx1, fmaxf(sacc[j][2], sacc[j][3]));
            }
            mx0 = fmaxf(mx0, __shfl_xor_sync(0xffffffff, mx0, 1));
            mx0 = fmaxf(mx0, __shfl_xor_sync(0xffffffff, mx0, 2));
            mx1 = fmaxf(mx1, __shfl_xor_sync(0xffffffff, mx1, 1));
            mx1 = fmaxf(mx1, __shfl_xor_sync(0xffffffff, mx1, 2));

            float mn0 = fmaxf(m0, mx0), mn1 = fmaxf(m1, mx1);
            float c0 = fast_exp2(m0 - mn0), c1 = fast_exp2(m1 - mn1);
            m0 = mn0; m1 = mn1;

            float s0 = 0.f, s1 = 0.f;
#pragma unroll
            for (int j = 0; j < 8; j++) {
                float p00 = fast_exp2(sacc[j][0] - mn0);
                float p01 = fast_exp2(sacc[j][1] - mn0);
                float p10 = fast_exp2(sacc[j][2] - mn1);
                float p11 = fast_exp2(sacc[j][3] - mn1);
                s0 += p00 + p01; s1 += p10 + p11;
                *(uint2*)&Phi[(r0)     * PSTR + j * 8 + 2 * qid] =
                    make_uint2(to_tf32(p00), to_tf32(p01));
                *(uint2*)&Phi[(r0 + 8) * PSTR + j * 8 + 2 * qid] =
                    make_uint2(to_tf32(p10), to_tf32(p11));
                oacc[j][0] *= c0; oacc[j][1] *= c0;
                oacc[j][2] *= c1; oacc[j][3] *= c1;
            }
            s0 += __shfl_xor_sync(0xffffffff, s0, 1);
            s0 += __shfl_xor_sync(0xffffffff, s0, 2);
            s1 += __shfl_xor_sync(0xffffffff, s1, 1);
            s1 += __shfl_xor_sync(0xffffffff, s1, 2);
            l0 = l0 * c0 + s0;
            l1 = l1 * c1 + s1;
        }

        if (t < 31) cp_wait1(); else cp_wait0();   // V(t) ready (K(t+1) may fly)
        __syncthreads();

        // ---- O += P @ V (2-pass: Phi*Vhi + Phi*Vlo) ----
#pragma unroll
        for (int k = 0; k < 8; k++) {
            const int kk = k * 8;
            uint32_t ah[4];
            ah[0] = Phi[(r0)     * PSTR + kk + qid];
            ah[1] = Phi[(r0 + 8) * PSTR + kk + qid];
            ah[2] = Phi[(r0)     * PSTR + kk + qid + 4];
            ah[3] = Phi[(r0 + 8) * PSTR + kk + qid + 4];
#pragma unroll
            for (int j = 0; j < 8; j++) {
                int n = j * 8 + grp;
                uint2 v0 = Vp[(kk + qid)     * VSTR2 + n];   // (hi, lo)
                uint2 v1 = Vp[(kk + qid + 4) * VSTR2 + n];
                mma_tf32(oacc[j][0], oacc[j][1], oacc[j][2], oacc[j][3],
                         ah[0], ah[1], ah[2], ah[3], v0.x, v1.x);
                mma_tf32(oacc[j][0], oacc[j][1], oacc[j][2], oacc[j][3],
                         ah[0], ah[1], ah[2], ah[3], v0.y, v1.y);
            }
        }
        __syncthreads();                 // all warps done reading V tile
        if (t + 1 < 32) stageV(t + 1);
    }

    // Epilogue: normalize, round to tf32 (out-proj GEMM needs no cvt)
    {
        float inv0 = 1.f / l0, inv1 = 1.f / l1;
        float* op0 = g_O + (size_t)(b * Sc + q0blk + r0) * Dc + h * HDc;
        float* op1 = g_O + (size_t)(b * Sc + q0blk + r0 + 8) * Dc + h * HDc;
#pragma unroll
        for (int j = 0; j < 8; j++) {
            *(float2*)&op0[j * 8 + 2 * qid] = make_float2(
                __uint_as_float(to_tf32(oacc[j][0] * inv0)),
                __uint_as_float(to_tf32(oacc[j][1] * inv0)));
            *(float2*)&op1[j * 8 + 2 * qid] = make_float2(
                __uint_as_float(to_tf32(oacc[j][2] * inv1)),
                __uint_as_float(to_tf32(oacc[j][3] * inv1)));
        }
    }
}

// ---------------------------------------------------------------------------
extern "C" void kernel_launch(void* const* d_in, const int* in_sizes, int n_in,
                              void* d_out, int out_size) {
    const float* X  = (const float*)d_in[0];
    const float* Wq = (const float*)d_in[1];
    const float* Wk = (const float*)d_in[2];
    const float* Wv = (const float*)d_in[3];
    const float* Wo = (const float*)d_in[4];
    float* out = (float*)d_out;

    uint32_t* Qh;
    uint2 *Khl, *Vhl;
    float *Ob, *Xr, *Wqr, *Wkr, *Wvr, *Wor;
    cudaGetSymbolAddress((void**)&Qh,  g_Qhi);
    cudaGetSymbolAddress((void**)&Khl, g_Khl);
    cudaGetSymbolAddress((void**)&Vhl, g_Vhl);
    cudaGetSymbolAddress((void**)&Ob,  g_O);
    cudaGetSymbolAddress((void**)&Xr,  g_Xr);
    cudaGetSymbolAddress((void**)&Wqr, g_Wqr);
    cudaGetSymbolAddress((void**)&Wkr, g_Wkr);
    cudaGetSymbolAddress((void**)&Wvr, g_Wvr);
    cudaGetSymbolAddress((void**)&Wor, g_Wor);

    cudaFuncSetAttribute(flash_attn_tc4, cudaFuncAttributeMaxDynamicSharedMemorySize, ATT_SMEM);

    const int M = Bc * Sc;         // 4096
    const size_t nX = (size_t)M * Dc;
    const size_t nWq = (size_t)Dc * Dc;
    const size_t nWk = (size_t)Dc * KVHc * HDc;

    // tf32 pre-rounding (keeps cvt.rna out of all GEMM hot loops)
    round_tf32<<<(int)(nX  / 1024), 256>>>(X,  Xr,  nX);
    round_tf32<<<(int)(nWq / 1024), 256>>>(Wq, Wqr, nWq);
    round_tf32<<<(int)(nWk / 1024), 256>>>(Wk, Wkr, nWk);
    round_tf32<<<(int)(nWk / 1024), 256>>>(Wv, Wvr, nWk);
    round_tf32<<<(int)(nWq / 1024), 256>>>(Wo, Wor, nWq);

    // Projections (Q folds softmax scale in log2 domain; K/V write (hi,lo) pairs)
    tf32gemm_hi<<<dim3(Dc / 128, M / 128), 256>>>(Xr, Wqr, Qh, SCALE * LOG2E, M, Dc, Dc);
    tf32gemm_hl<<<dim3((KVHc * HDc) / 128, M / 128), 256>>>(Xr, Wkr, Khl, M, KVHc * HDc, Dc);
    tf32gemm_hl<<<dim3((KVHc * HDc) / 128, M / 128), 256>>>(Xr, Wvr, Vhl, M, KVHc * HDc, Dc);

    flash_attn_tc4<<<dim3(Sc / 64, Hc, Bc), 128, ATT_SMEM>>>();

    tf32gemm<<<dim3(Dc / 128, M / 128), 256>>>(Ob, Wor, out, M, Dc, Dc);
}

// round 15
// speedup vs baseline: 3.8022x; 1.2966x over previous
#include <cuda_runtime.h>
#include <cstdint>

// Problem constants
constexpr int Bc  = 2;
constexpr int Sc  = 2048;
constexpr int Dc  = 2048;
constexpr int Hc  = 32;
constexpr int KVHc = 8;
constexpr int HDc = 64;
constexpr float SCALE = 0.125f;   // 1/sqrt(64)
constexpr float LOG2E = 1.4426950408889634f;

// Scratch (allocation-free rule: __device__ globals)
__device__ uint32_t g_Qhi[(size_t)Bc * Sc * Dc];                // Q tf32 bits (prescaled)
__device__ uint32_t g_Khi[(size_t)Bc * Sc * KVHc * HDc];        // K tf32 bits
__device__ uint32_t g_Vhi[(size_t)Bc * Sc * KVHc * HDc];        // V tf32 bits
__device__ float    g_O  [(size_t)Bc * Sc * Dc];                // tf32-rounded by epilogue
// tf32-rounded copies of raw inputs (GEMM hot loops need no cvt)
__device__ float g_Xr [(size_t)Bc * Sc * Dc];
__device__ float g_Wqr[(size_t)Dc * Dc];
__device__ float g_Wkr[(size_t)Dc * KVHc * HDc];
__device__ float g_Wvr[(size_t)Dc * KVHc * HDc];
__device__ float g_Wor[(size_t)Dc * Dc];

// ---------------------------------------------------------------------------
// Common PTX helpers
// ---------------------------------------------------------------------------
__device__ __forceinline__ void cp16(void* smem, const void* gmem) {
    uint32_t s = (uint32_t)__cvta_generic_to_shared(smem);
    asm volatile("cp.async.cg.shared.global [%0], [%1], 16;\n" :: "r"(s), "l"(gmem));
}
__device__ __forceinline__ void cp_commit() { asm volatile("cp.async.commit_group;\n"); }
__device__ __forceinline__ void cp_wait0()  { asm volatile("cp.async.wait_group 0;\n"); }
__device__ __forceinline__ void cp_wait1()  { asm volatile("cp.async.wait_group 1;\n"); }

__device__ __forceinline__ uint32_t to_tf32(float f) {
    uint32_t r;
    asm("cvt.rna.tf32.f32 %0, %1;" : "=r"(r) : "f"(f));
    return r;
}

__device__ __forceinline__ void mma_tf32(float& c0, float& c1, float& c2, float& c3,
                                         uint32_t a0, uint32_t a1, uint32_t a2, uint32_t a3,
                                         uint32_t b0, uint32_t b1) {
    asm volatile(
        "mma.sync.aligned.m16n8k8.row.col.f32.tf32.tf32.f32 "
        "{%0,%1,%2,%3}, {%4,%5,%6,%7}, {%8,%9}, {%0,%1,%2,%3};\n"
        : "+f"(c0), "+f"(c1), "+f"(c2), "+f"(c3)
        : "r"(a0), "r"(a1), "r"(a2), "r"(a3), "r"(b0), "r"(b1));
}

// Fast 2^y for y <= 0 (FMA pipe only, no MUFU). Rel err ~4e-5.
__device__ __forceinline__ float fast_exp2(float y) {
    y = fmaxf(y, -80.f);
    float t = y + 12582912.f;
    int k = __float_as_int(t) - 0x4B400000;
    float f = y - (t - 12582912.f);
    float r = fmaf(f, 0.0096181291f, 0.0555041087f);
    r = fmaf(f, r, 0.2402265069f);
    r = fmaf(f, r, 0.6931471806f);
    r = fmaf(f, r, 1.0f);
    return __int_as_float(__float_as_int(r) + (k << 23));
}

// ---------------------------------------------------------------------------
// Elementwise tf32 rounding pre-pass (n multiple of 1024)
// ---------------------------------------------------------------------------
__global__ __launch_bounds__(256) void round_tf32(const float* __restrict__ in,
                                                  float* __restrict__ out, size_t n) {
    size_t i = ((size_t)blockIdx.x * 256 + threadIdx.x) * 4;
    if (i >= n) return;
    float4 v = *(const float4*)(in + i);
    v.x = __uint_as_float(to_tf32(v.x));
    v.y = __uint_as_float(to_tf32(v.y));
    v.z = __uint_as_float(to_tf32(v.z));
    v.w = __uint_as_float(to_tf32(v.w));
    *(float4*)(out + i) = v;
}

// ---------------------------------------------------------------------------
// TF32 GEMM core (128x128 tile, BK=16, 8 warps, m16n8k8).
// Inputs MUST be pre-rounded to tf32 -> no cvt in the hot loop.
// ---------------------------------------------------------------------------
constexpr int ASTRIDE = 20;
constexpr int BSTRIDE = 136;
constexpr int ABUF = 128 * ASTRIDE;
constexpr int BBUF = 16 * BSTRIDE;

#define GEMM_BODY                                                                   \
    __shared__ float As[2][ABUF];                                                   \
    __shared__ float Bs[2][BBUF];                                                   \
    const int tid  = threadIdx.x;                                                   \
    const int warp = tid >> 5;                                                      \
    const int lane = tid & 31;                                                      \
    const int grp  = lane >> 2;                                                     \
    const int qid  = lane & 3;                                                      \
    const int warpM = warp >> 2;                                                    \
    const int warpN = warp & 3;                                                     \
    const int bx = blockIdx.x;                                                      \
    const int by = blockIdx.y;                                                      \
    const int numTiles = K / 16;                                                    \
    auto load_tile = [&](int t, int s) {                                            \
        int k0 = t * 16;                                                            \
        {                                                                           \
            int r = tid >> 2, cc = tid & 3;                                         \
            cp16(&As[s][r * ASTRIDE + cc * 4],                                      \
                 A + (size_t)(by * 128 + r) * K + k0 + cc * 4);                     \
            r = (tid + 256) >> 2; cc = (tid + 256) & 3;                             \
            cp16(&As[s][r * ASTRIDE + cc * 4],                                      \
                 A + (size_t)(by * 128 + r) * K + k0 + cc * 4);                     \
        }                                                                           \
        {                                                                           \
            int r = tid >> 5, cc = tid & 31;                                        \
            cp16(&Bs[s][r * BSTRIDE + cc * 4],                                      \
                 Bm + (size_t)(k0 + r) * N + bx * 128 + cc * 4);                    \
            r = (tid + 256) >> 5; cc = (tid + 256) & 31;                            \
            cp16(&Bs[s][r * BSTRIDE + cc * 4],                                      \
                 Bm + (size_t)(k0 + r) * N + bx * 128 + cc * 4);                    \
        }                                                                           \
        cp_commit();                                                                \
    };                                                                              \
    float acc[4][4][4];                                                             \
    _Pragma("unroll")                                                               \
    for (int i = 0; i < 4; i++)                                                     \
        _Pragma("unroll")                                                           \
        for (int j = 0; j < 4; j++)                                                 \
            _Pragma("unroll")                                                       \
            for (int r = 0; r < 4; r++) acc[i][j][r] = 0.f;                         \
    load_tile(0, 0);                                                                \
    for (int t = 0; t < numTiles; t++) {                                            \
        cp_wait0();                                                                 \
        __syncthreads();                                                            \
        if (t + 1 < numTiles) load_tile(t + 1, (t + 1) & 1);                        \
        const uint32_t* Asb = (const uint32_t*)As[t & 1];                           \
        const uint32_t* Bsb = (const uint32_t*)Bs[t & 1];                           \
        _Pragma("unroll")                                                           \
        for (int kk = 0; kk < 16; kk += 8) {                                        \
            uint32_t af[4][4];                                                      \
            _Pragma("unroll")                                                       \
            for (int i = 0; i < 4; i++) {                                           \
                int mr = warpM * 64 + i * 16 + grp;                                 \
                af[i][0] = Asb[(mr)     * ASTRIDE + kk + qid];                      \
                af[i][1] = Asb[(mr + 8) * ASTRIDE + kk + qid];                      \
                af[i][2] = Asb[(mr)     * ASTRIDE + kk + qid + 4];                  \
                af[i][3] = Asb[(mr + 8) * ASTRIDE + kk + qid + 4];                  \
            }                                                                       \
            uint32_t bf[4][2];                                                      \
            _Pragma("unroll")                                                       \
            for (int j = 0; j < 4; j++) {                                           \
                int nc = warpN * 32 + j * 8 + grp;                                  \
                bf[j][0] = Bsb[(kk + qid)     * BSTRIDE + nc];                      \
                bf[j][1] = Bsb[(kk + qid + 4) * BSTRIDE + nc];                      \
            }                                                                       \
            _Pragma("unroll")                                                       \
            for (int i = 0; i < 4; i++)                                             \
                _Pragma("unroll")                                                   \
                for (int j = 0; j < 4; j++)                                         \
                    mma_tf32(acc[i][j][0], acc[i][j][1], acc[i][j][2], acc[i][j][3],\
                             af[i][0], af[i][1], af[i][2], af[i][3],                \
                             bf[j][0], bf[j][1]);                                   \
        }                                                                           \
        __syncthreads();                                                            \
    }

__global__ __launch_bounds__(256) void tf32gemm(const float* __restrict__ A,
                                                const float* __restrict__ Bm,
                                                float* __restrict__ C,
                                                int M, int N, int K) {
    GEMM_BODY
#pragma unroll
    for (int i = 0; i < 4; i++) {
        int mr = by * 128 + warpM * 64 + i * 16 + grp;
#pragma unroll
        for (int j = 0; j < 4; j++) {
            int nc = bx * 128 + warpN * 32 + j * 8 + 2 * qid;
            *(float2*)&C[(size_t)mr * N + nc]       = make_float2(acc[i][j][0], acc[i][j][1]);
            *(float2*)&C[(size_t)(mr + 8) * N + nc] = make_float2(acc[i][j][2], acc[i][j][3]);
        }
    }
}

// Epilogue: tf32 hi bits, prescaled (used for Q, K, V)
__global__ __launch_bounds__(256) void tf32gemm_hi(const float* __restrict__ A,
                                                   const float* __restrict__ Bm,
                                                   uint32_t* __restrict__ Chi,
                                                   float prescale,
                                                   int M, int N, int K) {
    GEMM_BODY
#pragma unroll
    for (int i = 0; i < 4; i++) {
        int mr = by * 128 + warpM * 64 + i * 16 + grp;
#pragma unroll
        for (int j = 0; j < 4; j++) {
            int nc = bx * 128 + warpN * 32 + j * 8 + 2 * qid;
            *(uint2*)&Chi[(size_t)mr * N + nc] =
                make_uint2(to_tf32(acc[i][j][0] * prescale), to_tf32(acc[i][j][1] * prescale));
            *(uint2*)&Chi[(size_t)(mr + 8) * N + nc] =
                make_uint2(to_tf32(acc[i][j][2] * prescale), to_tf32(acc[i][j][3] * prescale));
        }
    }
}

// ---------------------------------------------------------------------------
// Tensor-core flash attention, single-pass tf32 (Q/K/V/P all tf32-rounded).
// K(t+1) prefetched during softmax+PV; V(t+1) after PV; split wait_groups.
// CTA: 64 queries x 1 head, 128 threads (4 warps). smem 53 KB -> 3 CTAs/SM.
// ---------------------------------------------------------------------------
constexpr int KSTR = 68;   // u32 stride per K row: banks 4*grp+qid, conflict-free
constexpr int VSTR = 72;   // u32 stride per V row: banks 8*qid+grp, conflict-free
constexpr int PSTR = 72;   // u32 stride per P row: STS.64-clean
constexpr int ATT_SMEM = (64 * KSTR + 64 * VSTR + 64 * PSTR) * 4;  // 54272 B

__global__ __launch_bounds__(128) void flash_attn_tc5() {
    extern __shared__ uint32_t smu[];
    uint32_t* Kp  = smu;
    uint32_t* Vp  = Kp + 64 * KSTR;
    uint32_t* Phi = Vp + 64 * VSTR;

    const int tid  = threadIdx.x;
    const int warp = tid >> 5;
    const int lane = tid & 31;
    const int grp  = lane >> 2;
    const int qid  = lane & 3;
    const int h = blockIdx.y, b = blockIdx.z;
    const int g = h >> 2;
    const int q0blk = blockIdx.x * 64;

    const int r0 = warp * 16 + grp;

    auto stageK = [&](int t) {
#pragma unroll
        for (int i = 0; i < 8; i++) {
            int c = tid + i * 128;            // 0..1023 chunks of 16B
            int row = c >> 4, cc = (c & 15) * 4;
            size_t gb = (size_t)(b * Sc + t * 64 + row) * (KVHc * HDc) + g * HDc + cc;
            cp16(&Kp[row * KSTR + cc], g_Khi + gb);
        }
        cp_commit();
    };
    auto stageV = [&](int t) {
#pragma unroll
        for (int i = 0; i < 8; i++) {
            int c = tid + i * 128;
            int row = c >> 4, cc = (c & 15) * 4;
            size_t gb = (size_t)(b * Sc + t * 64 + row) * (KVHc * HDc) + g * HDc + cc;
            cp16(&Vp[row * VSTR + cc], g_Vhi + gb);
        }
        cp_commit();
    };

    // Q fragments (prescaled tf32 hi) -> registers, loop-invariant
    uint32_t qh[8][4];
    {
        const size_t base = (size_t)(b * Sc + q0blk + r0) * Dc + h * HDc;
        const size_t row8 = (size_t)8 * Dc;
#pragma unroll
        for (int k = 0; k < 8; k++) {
            int c0 = k * 8 + qid;
            qh[k][0] = g_Qhi[base + c0];
            qh[k][1] = g_Qhi[base + row8 + c0];
            qh[k][2] = g_Qhi[base + c0 + 4];
            qh[k][3] = g_Qhi[base + row8 + c0 + 4];
        }
    }

    float oacc[8][4];
#pragma unroll
    for (int j = 0; j < 8; j++)
#pragma unroll
        for (int r = 0; r < 4; r++) oacc[j][r] = 0.f;
    float m0 = -1e30f, m1 = -1e30f, l0 = 0.f, l1 = 0.f;

    stageK(0);
    stageV(0);

    for (int t = 0; t < 32; t++) {
        cp_wait1();          // K(t) ready (V(t) may still be in flight)
        __syncthreads();

        // ---- S = Q @ K^T (single-pass tf32) ----
        float sacc[8][4];
#pragma unroll
        for (int j = 0; j < 8; j++)
#pragma unroll
            for (int r = 0; r < 4; r++) sacc[j][r] = 0.f;

#pragma unroll
        for (int k = 0; k < 8; k++) {
            const int kk = k * 8;
#pragma unroll
            for (int j = 0; j < 8; j++) {
                int n = j * 8 + grp;
                uint32_t b0 = Kp[n * KSTR + kk + qid];
                uint32_t b1 = Kp[n * KSTR + kk + qid + 4];
                mma_tf32(sacc[j][0], sacc[j][1], sacc[j][2], sacc[j][3],
                         qh[k][0], qh[k][1], qh[k][2], qh[k][3], b0, b1);
            }
        }
        __syncthreads();                 // all warps done reading K tile
        if (t + 1 < 32) stageK(t + 1);   // K prefetch hides behind softmax+PV

        // ---- online softmax (log2 domain); P (tf32) -> Phi ----
        {
            float mx0 = -1e30f, mx1 = -1e30f;
#pragma unroll
            for (int j = 0; j < 8; j++) {
                mx0 = fmaxf(mx0, fmaxf(sacc[j][0], sacc[j][1]));
                mx1 = fmaxf(mx1, fmaxf(sacc[j][2], sacc[j][3]));
            }
            mx0 = fmaxf(mx0, __shfl_xor_sync(0xffffffff, mx0, 1));
            mx0 = fmaxf(mx0, __shfl_xor_sync(0xffffffff, mx0, 2));
            mx1 = fmaxf(mx1, __shfl_xor_sync(0xffffffff, mx1, 1));
            mx1 = fmaxf(mx1, __shfl_xor_sync(0xffffffff, mx1, 2));

            float mn0 = fmaxf(m0, mx0), mn1 = fmaxf(m1, mx1);
            float c0 = fast_exp2(m0 - mn0), c1 = fast_exp2(m1 - mn1);
            m0 = mn0; m1 = mn1;

            float s0 = 0.f, s1 = 0.f;
#pragma unroll
            for (int j = 0; j < 8; j++) {
                float p00 = fast_exp2(sacc[j][0] - mn0);
                float p01 = fast_exp2(sacc[j][1] - mn0);
                float p10 = fast_exp2(sacc[j][2] - mn1);
                float p11 = fast_exp2(sacc[j][3] - mn1);
                s0 += p00 + p01; s1 += p10 + p11;
                *(uint2*)&Phi[(r0)     * PSTR + j * 8 + 2 * qid] =
                    make_uint2(to_tf32(p00), to_tf32(p01));
                *(uint2*)&Phi[(r0 + 8) * PSTR + j * 8 + 2 * qid] =
                    make_uint2(to_tf32(p10), to_tf32(p11));
                oacc[j][0] *= c0; oacc[j][1] *= c0;
                oacc[j][2] *= c1; oacc[j][3] *= c1;
            }
            s0 += __shfl_xor_sync(0xffffffff, s0, 1);
            s0 += __shfl_xor_sync(0xffffffff, s0, 2);
            s1 += __shfl_xor_sync(0xffffffff, s1, 1);
            s1 += __shfl_xor_sync(0xffffffff, s1, 2);
            l0 = l0 * c0 + s0;
            l1 = l1 * c1 + s1;
        }

        if (t < 31) cp_wait1(); else cp_wait0();   // V(t) ready (K(t+1) may fly)
        __syncthreads();

        // ---- O += P @ V (single-pass tf32) ----
#pragma unroll
        for (int k = 0; k < 8; k++) {
            const int kk = k * 8;
            uint32_t ah[4];
            ah[0] = Phi[(r0)     * PSTR + kk + qid];
            ah[1] = Phi[(r0 + 8) * PSTR + kk + qid];
            ah[2] = Phi[(r0)     * PSTR + kk + qid + 4];
            ah[3] = Phi[(r0 + 8) * PSTR + kk + qid + 4];
#pragma unroll
            for (int j = 0; j < 8; j++) {
                int n = j * 8 + grp;
                uint32_t v0 = Vp[(kk + qid)     * VSTR + n];
                uint32_t v1 = Vp[(kk + qid + 4) * VSTR + n];
                mma_tf32(oacc[j][0], oacc[j][1], oacc[j][2], oacc[j][3],
                         ah[0], ah[1], ah[2], ah[3], v0, v1);
            }
        }
        __syncthreads();                 // all warps done reading V tile
        if (t + 1 < 32) stageV(t + 1);
    }

    // Epilogue: normalize, round to tf32 (out-proj GEMM needs no cvt)
    {
        float inv0 = 1.f / l0, inv1 = 1.f / l1;
        float* op0 = g_O + (size_t)(b * Sc + q0blk + r0) * Dc + h * HDc;
        float* op1 = g_O + (size_t)(b * Sc + q0blk + r0 + 8) * Dc + h * HDc;
#pragma unroll
        for (int j = 0; j < 8; j++) {
            *(float2*)&op0[j * 8 + 2 * qid] = make_float2(
                __uint_as_float(to_tf32(oacc[j][0] * inv0)),
                __uint_as_float(to_tf32(oacc[j][1] * inv0)));
            *(float2*)&op1[j * 8 + 2 * qid] = make_float2(
                __uint_as_float(to_tf32(oacc[j][2] * inv1)),
                __uint_as_float(to_tf32(oacc[j][3] * inv1)));
        }
    }
}

// ---------------------------------------------------------------------------
extern "C" void kernel_launch(void* const* d_in, const int* in_sizes, int n_in,
                              void* d_out, int out_size) {
    const float* X  = (const float*)d_in[0];
    const float* Wq = (const float*)d_in[1];
    const float* Wk = (const float*)d_in[2];
    const float* Wv = (const float*)d_in[3];
    const float* Wo = (const float*)d_in[4];
    float* out = (float*)d_out;

    uint32_t *Qh, *Kh, *Vh;
    float *Ob, *Xr, *Wqr, *Wkr, *Wvr, *Wor;
    cudaGetSymbolAddress((void**)&Qh,  g_Qhi);
    cudaGetSymbolAddress((void**)&Kh,  g_Khi);
    cudaGetSymbolAddress((void**)&Vh,  g_Vhi);
    cudaGetSymbolAddress((void**)&Ob,  g_O);
    cudaGetSymbolAddress((void**)&Xr,  g_Xr);
    cudaGetSymbolAddress((void**)&Wqr, g_Wqr);
    cudaGetSymbolAddress((void**)&Wkr, g_Wkr);
    cudaGetSymbolAddress((void**)&Wvr, g_Wvr);
    cudaGetSymbolAddress((void**)&Wor, g_Wor);

    cudaFuncSetAttribute(flash_attn_tc5, cudaFuncAttributeMaxDynamicSharedMemorySize, ATT_SMEM);

    const int M = Bc * Sc;         // 4096
    const size_t nX = (size_t)M * Dc;
    const size_t nWq = (size_t)Dc * Dc;
    const size_t nWk = (size_t)Dc * KVHc * HDc;

    // tf32 pre-rounding (keeps cvt.rna out of all GEMM hot loops)
    round_tf32<<<(int)(nX  / 1024), 256>>>(X,  Xr,  nX);
    round_tf32<<<(int)(nWq / 1024), 256>>>(Wq, Wqr, nWq);
    round_tf32<<<(int)(nWk / 1024), 256>>>(Wk, Wkr, nWk);
    round_tf32<<<(int)(nWk / 1024), 256>>>(Wv, Wvr, nWk);
    round_tf32<<<(int)(nWq / 1024), 256>>>(Wo, Wor, nWq);

    // Projections (Q folds softmax scale in log2 domain; K/V tf32 hi bits)
    tf32gemm_hi<<<dim3(Dc / 128, M / 128), 256>>>(Xr, Wqr, Qh, SCALE * LOG2E, M, Dc, Dc);
    tf32gemm_hi<<<dim3((KVHc * HDc) / 128, M / 128), 256>>>(Xr, Wkr, Kh, 1.f, M, KVHc * HDc, Dc);
    tf32gemm_hi<<<dim3((KVHc * HDc) / 128, M / 128), 256>>>(Xr, Wvr, Vh, 1.f, M, KVHc * HDc, Dc);

    flash_attn_tc5<<<dim3(Sc / 64, Hc, Bc), 128, ATT_SMEM>>>();

    tf32gemm<<<dim3(Dc / 128, M / 128), 256>>>(Ob, Wor, out, M, Dc, Dc);
}

// round 16
// speedup vs baseline: 4.1145x; 1.0821x over previous
#include <cuda_runtime.h>
#include <cstdint>

// Problem constants
constexpr int Bc  = 2;
constexpr int Sc  = 2048;
constexpr int Dc  = 2048;
constexpr int Hc  = 32;
constexpr int KVHc = 8;
constexpr int HDc = 64;
constexpr float SCALE = 0.125f;   // 1/sqrt(64)
constexpr float LOG2E = 1.4426950408889634f;

constexpr int NQKV = Dc + 2 * KVHc * HDc;   // 3072 fused projection width
constexpr int KOFF = Dc;                    // K column offset in fused buffer
constexpr int VOFF = Dc + KVHc * HDc;       // V column offset

// Scratch (allocation-free rule: __device__ globals)
__device__ uint32_t g_QKV[(size_t)Bc * Sc * NQKV];   // tf32 bits: [Q | K | V] per row
__device__ float    g_O  [(size_t)Bc * Sc * Dc];     // tf32-rounded by epilogue
// tf32-rounded inputs (GEMM hot loops need no cvt)
__device__ float g_Xr  [(size_t)Bc * Sc * Dc];
__device__ float g_Wqkv[(size_t)Dc * NQKV];          // [Wq | Wk | Wv] columns
__device__ float g_Wor [(size_t)Dc * Dc];

// ---------------------------------------------------------------------------
// Common PTX helpers
// ---------------------------------------------------------------------------
__device__ __forceinline__ void cp16(void* smem, const void* gmem) {
    uint32_t s = (uint32_t)__cvta_generic_to_shared(smem);
    asm volatile("cp.async.cg.shared.global [%0], [%1], 16;\n" :: "r"(s), "l"(gmem));
}
__device__ __forceinline__ void cp_commit() { asm volatile("cp.async.commit_group;\n"); }
__device__ __forceinline__ void cp_wait0()  { asm volatile("cp.async.wait_group 0;\n"); }
__device__ __forceinline__ void cp_wait1()  { asm volatile("cp.async.wait_group 1;\n"); }

__device__ __forceinline__ uint32_t to_tf32(float f) {
    uint32_t r;
    asm("cvt.rna.tf32.f32 %0, %1;" : "=r"(r) : "f"(f));
    return r;
}

__device__ __forceinline__ void mma_tf32(float& c0, float& c1, float& c2, float& c3,
                                         uint32_t a0, uint32_t a1, uint32_t a2, uint32_t a3,
                                         uint32_t b0, uint32_t b1) {
    asm volatile(
        "mma.sync.aligned.m16n8k8.row.col.f32.tf32.tf32.f32 "
        "{%0,%1,%2,%3}, {%4,%5,%6,%7}, {%8,%9}, {%0,%1,%2,%3};\n"
        : "+f"(c0), "+f"(c1), "+f"(c2), "+f"(c3)
        : "r"(a0), "r"(a1), "r"(a2), "r"(a3), "r"(b0), "r"(b1));
}

// Fast 2^y for y <= 0 (FMA pipe only, no MUFU). Rel err ~4e-5.
__device__ __forceinline__ float fast_exp2(float y) {
    y = fmaxf(y, -80.f);
    float t = y + 12582912.f;
    int k = __float_as_int(t) - 0x4B400000;
    float f = y - (t - 12582912.f);
    float r = fmaf(f, 0.0096181291f, 0.0555041087f);
    r = fmaf(f, r, 0.2402265069f);
    r = fmaf(f, r, 0.6931471806f);
    r = fmaf(f, r, 1.0f);
    return __int_as_float(__float_as_int(r) + (k << 23));
}

// ---------------------------------------------------------------------------
// tf32 rounding pre-passes
// ---------------------------------------------------------------------------
__global__ __launch_bounds__(256) void round_tf32(const float* __restrict__ in,
                                                  float* __restrict__ out, size_t n) {
    size_t i = ((size_t)blockIdx.x * 256 + threadIdx.x) * 4;
    if (i >= n) return;
    float4 v = *(const float4*)(in + i);
    v.x = __uint_as_float(to_tf32(v.x));
    v.y = __uint_as_float(to_tf32(v.y));
    v.z = __uint_as_float(to_tf32(v.z));
    v.w = __uint_as_float(to_tf32(v.w));
    *(float4*)(out + i) = v;
}

// Round + scatter rows into the concatenated weight buffer:
// in [rows x ncols] row-major -> out[row * NQKV + coloff + col]
__global__ __launch_bounds__(256) void round_tf32_cat(const float* __restrict__ in,
                                                      float* __restrict__ out,
                                                      int ncols, int coloff, size_t n) {
    size_t i = ((size_t)blockIdx.x * 256 + threadIdx.x) * 4;
    if (i >= n) return;
    float4 v = *(const float4*)(in + i);
    v.x = __uint_as_float(to_tf32(v.x));
    v.y = __uint_as_float(to_tf32(v.y));
    v.z = __uint_as_float(to_tf32(v.z));
    v.w = __uint_as_float(to_tf32(v.w));
    int row = (int)(i / ncols);
    int col = (int)(i % ncols);
    *(float4*)(out + (size_t)row * NQKV + coloff + col) = v;
}

// ---------------------------------------------------------------------------
// TF32 GEMM core (128x128 tile, BK=16, 8 warps, m16n8k8).
// Inputs MUST be pre-rounded to tf32 -> no cvt in the hot loop.
// ---------------------------------------------------------------------------
constexpr int ASTRIDE = 20;
constexpr int BSTRIDE = 136;
constexpr int ABUF = 128 * ASTRIDE;
constexpr int BBUF = 16 * BSTRIDE;

#define GEMM_BODY                                                                   \
    __shared__ float As[2][ABUF];                                                   \
    __shared__ float Bs[2][BBUF];                                                   \
    const int tid  = threadIdx.x;                                                   \
    const int warp = tid >> 5;                                                      \
    const int lane = tid & 31;                                                      \
    const int grp  = lane >> 2;                                                     \
    const int qid  = lane & 3;                                                      \
    const int warpM = warp >> 2;                                                    \
    const int warpN = warp & 3;                                                     \
    const int bx = blockIdx.x;                                                      \
    const int by = blockIdx.y;                                                      \
    const int numTiles = K / 16;                                                    \
    auto load_tile = [&](int t, int s) {                                            \
        int k0 = t * 16;                                                            \
        {                                                                           \
            int r = tid >> 2, cc = tid & 3;                                         \
            cp16(&As[s][r * ASTRIDE + cc * 4],                                      \
                 A + (size_t)(by * 128 + r) * K + k0 + cc * 4);                     \
            r = (tid + 256) >> 2; cc = (tid + 256) & 3;                             \
            cp16(&As[s][r * ASTRIDE + cc * 4],                                      \
                 A + (size_t)(by * 128 + r) * K + k0 + cc * 4);                     \
        }                                                                           \
        {                                                                           \
            int r = tid >> 5, cc = tid & 31;                                        \
            cp16(&Bs[s][r * BSTRIDE + cc * 4],                                      \
                 Bm + (size_t)(k0 + r) * N + bx * 128 + cc * 4);                    \
            r = (tid + 256) >> 5; cc = (tid + 256) & 31;                            \
            cp16(&Bs[s][r * BSTRIDE + cc * 4],                                      \
                 Bm + (size_t)(k0 + r) * N + bx * 128 + cc * 4);                    \
        }                                                                           \
        cp_commit();                                                                \
    };                                                                              \
    float acc[4][4][4];                                                             \
    _Pragma("unroll")                                                               \
    for (int i = 0; i < 4; i++)                                                     \
        _Pragma("unroll")                                                           \
        for (int j = 0; j < 4; j++)                                                 \
            _Pragma("unroll")                                                       \
            for (int r = 0; r < 4; r++) acc[i][j][r] = 0.f;                         \
    load_tile(0, 0);                                                                \
    for (int t = 0; t < numTiles; t++) {                                            \
        cp_wait0();                                                                 \
        __syncthreads();                                                            \
        if (t + 1 < numTiles) load_tile(t + 1, (t + 1) & 1);                        \
        const uint32_t* Asb = (const uint32_t*)As[t & 1];                           \
        const uint32_t* Bsb = (const uint32_t*)Bs[t & 1];                           \
        _Pragma("unroll")                                                           \
        for (int kk = 0; kk < 16; kk += 8) {                                        \
            uint32_t af[4][4];                                                      \
            _Pragma("unroll")                                                       \
            for (int i = 0; i < 4; i++) {                                           \
                int mr = warpM * 64 + i * 16 + grp;                                 \
                af[i][0] = Asb[(mr)     * ASTRIDE + kk + qid];                      \
                af[i][1] = Asb[(mr + 8) * ASTRIDE + kk + qid];                      \
                af[i][2] = Asb[(mr)     * ASTRIDE + kk + qid + 4];                  \
                af[i][3] = Asb[(mr + 8) * ASTRIDE + kk + qid + 4];                  \
            }                                                                       \
            uint32_t bf[4][2];                                                      \
            _Pragma("unroll")                                                       \
            for (int j = 0; j < 4; j++) {                                           \
                int nc = warpN * 32 + j * 8 + grp;                                  \
                bf[j][0] = Bsb[(kk + qid)     * BSTRIDE + nc];                      \
                bf[j][1] = Bsb[(kk + qid + 4) * BSTRIDE + nc];                      \
            }                                                                       \
            _Pragma("unroll")                                                       \
            for (int i = 0; i < 4; i++)                                             \
                _Pragma("unroll")                                                   \
                for (int j = 0; j < 4; j++)                                         \
                    mma_tf32(acc[i][j][0], acc[i][j][1], acc[i][j][2], acc[i][j][3],\
                             af[i][0], af[i][1], af[i][2], af[i][3],                \
                             bf[j][0], bf[j][1]);                                   \
        }                                                                           \
        __syncthreads();                                                            \
    }

__global__ __launch_bounds__(256) void tf32gemm(const float* __restrict__ A,
                                                const float* __restrict__ Bm,
                                                float* __restrict__ C,
                                                int M, int N, int K) {
    GEMM_BODY
#pragma unroll
    for (int i = 0; i < 4; i++) {
        int mr = by * 128 + warpM * 64 + i * 16 + grp;
#pragma unroll
        for (int j = 0; j < 4; j++) {
            int nc = bx * 128 + warpN * 32 + j * 8 + 2 * qid;
            *(float2*)&C[(size_t)mr * N + nc]       = make_float2(acc[i][j][0], acc[i][j][1]);
            *(float2*)&C[(size_t)(mr + 8) * N + nc] = make_float2(acc[i][j][2], acc[i][j][3]);
        }
    }
}

// Fused QKV epilogue: tf32 hi bits; Q columns (bx < Dc/128) get qscale prescale.
__global__ __launch_bounds__(256) void tf32gemm_hi(const float* __restrict__ A,
                                                   const float* __restrict__ Bm,
                                                   uint32_t* __restrict__ Chi,
                                                   float qscale,
                                                   int M, int N, int K) {
    GEMM_BODY
    const float prescale = (bx < Dc / 128) ? qscale : 1.f;
#pragma unroll
    for (int i = 0; i < 4; i++) {
        int mr = by * 128 + warpM * 64 + i * 16 + grp;
#pragma unroll
        for (int j = 0; j < 4; j++) {
            int nc = bx * 128 + warpN * 32 + j * 8 + 2 * qid;
            *(uint2*)&Chi[(size_t)mr * N + nc] =
                make_uint2(to_tf32(acc[i][j][0] * prescale), to_tf32(acc[i][j][1] * prescale));
            *(uint2*)&Chi[(size_t)(mr + 8) * N + nc] =
                make_uint2(to_tf32(acc[i][j][2] * prescale), to_tf32(acc[i][j][3] * prescale));
        }
    }
}

// ---------------------------------------------------------------------------
// Tensor-core flash attention, single-pass tf32, reading the fused QKV buffer.
// K(t+1) prefetched during softmax+PV; V(t+1) after PV; split wait_groups.
// CTA: 64 queries x 1 head, 128 threads (4 warps). smem 53 KB -> 3 CTAs/SM.
// ---------------------------------------------------------------------------
constexpr int KSTR = 68;   // u32 stride per K row: banks 4*grp+qid, conflict-free
constexpr int VSTR = 72;   // u32 stride per V row: banks 8*qid+grp, conflict-free
constexpr int PSTR = 72;   // u32 stride per P row: STS.64-clean
constexpr int ATT_SMEM = (64 * KSTR + 64 * VSTR + 64 * PSTR) * 4;  // 54272 B

__global__ __launch_bounds__(128) void flash_attn_tc5() {
    extern __shared__ uint32_t smu[];
    uint32_t* Kp  = smu;
    uint32_t* Vp  = Kp + 64 * KSTR;
    uint32_t* Phi = Vp + 64 * VSTR;

    const int tid  = threadIdx.x;
    const int warp = tid >> 5;
    const int lane = tid & 31;
    const int grp  = lane >> 2;
    const int qid  = lane & 3;
    const int h = blockIdx.y, b = blockIdx.z;
    const int g = h >> 2;
    const int q0blk = blockIdx.x * 64;

    const int r0 = warp * 16 + grp;

    auto stageK = [&](int t) {
#pragma unroll
        for (int i = 0; i < 8; i++) {
            int c = tid + i * 128;            // 0..1023 chunks of 16B
            int row = c >> 4, cc = (c & 15) * 4;
            size_t gb = (size_t)(b * Sc + t * 64 + row) * NQKV + KOFF + g * HDc + cc;
            cp16(&Kp[row * KSTR + cc], g_QKV + gb);
        }
        cp_commit();
    };
    auto stageV = [&](int t) {
#pragma unroll
        for (int i = 0; i < 8; i++) {
            int c = tid + i * 128;
            int row = c >> 4, cc = (c & 15) * 4;
            size_t gb = (size_t)(b * Sc + t * 64 + row) * NQKV + VOFF + g * HDc + cc;
            cp16(&Vp[row * VSTR + cc], g_QKV + gb);
        }
        cp_commit();
    };

    // Q fragments (prescaled tf32 hi) -> registers, loop-invariant
    uint32_t qh[8][4];
    {
        const size_t base = (size_t)(b * Sc + q0blk + r0) * NQKV + h * HDc;
        const size_t row8 = (size_t)8 * NQKV;
#pragma unroll
        for (int k = 0; k < 8; k++) {
            int c0 = k * 8 + qid;
            qh[k][0] = g_QKV[base + c0];
            qh[k][1] = g_QKV[base + row8 + c0];
            qh[k][2] = g_QKV[base + c0 + 4];
            qh[k][3] = g_QKV[base + row8 + c0 + 4];
        }
    }

    float oacc[8][4];
#pragma unroll
    for (int j = 0; j < 8; j++)
#pragma unroll
        for (int r = 0; r < 4; r++) oacc[j][r] = 0.f;
    float m0 = -1e30f, m1 = -1e30f, l0 = 0.f, l1 = 0.f;

    stageK(0);
    stageV(0);

    for (int t = 0; t < 32; t++) {
        cp_wait1();          // K(t) ready (V(t) may still be in flight)
        __syncthreads();

        // ---- S = Q @ K^T (single-pass tf32) ----
        float sacc[8][4];
#pragma unroll
        for (int j = 0; j < 8; j++)
#pragma unroll
            for (int r = 0; r < 4; r++) sacc[j][r] = 0.f;

#pragma unroll
        for (int k = 0; k < 8; k++) {
            const int kk = k * 8;
#pragma unroll
            for (int j = 0; j < 8; j++) {
                int n = j * 8 + grp;
                uint32_t b0 = Kp[n * KSTR + kk + qid];
                uint32_t b1 = Kp[n * KSTR + kk + qid + 4];
                mma_tf32(sacc[j][0], sacc[j][1], sacc[j][2], sacc[j][3],
                         qh[k][0], qh[k][1], qh[k][2], qh[k][3], b0, b1);
            }
        }
        __syncthreads();                 // all warps done reading K tile
        if (t + 1 < 32) stageK(t + 1);   // K prefetch hides behind softmax+PV

        // ---- online softmax (log2 domain); P (tf32) -> Phi ----
        {
            float mx0 = -1e30f, mx1 = -1e30f;
#pragma unroll
            for (int j = 0; j < 8; j++) {
                mx0 = fmaxf(mx0, fmaxf(sacc[j][0], sacc[j][1]));
                mx1 = fmaxf(mx1, fmaxf(sacc[j][2], sacc[j][3]));
            }
            mx0 = fmaxf(mx0, __shfl_xor_sync(0xffffffff, mx0, 1));
            mx0 = fmaxf(mx0, __shfl_xor_sync(0xffffffff, mx0, 2));
            mx1 = fmaxf(mx1, __shfl_xor_sync(0xffffffff, mx1, 1));
            mx1 = fmaxf(mx1, __shfl_xor_sync(0xffffffff, mx1, 2));

            float mn0 = fmaxf(m0, mx0), mn1 = fmaxf(m1, mx1);
            float c0 = fast_exp2(m0 - mn0), c1 = fast_exp2(m1 - mn1);
            m0 = mn0; m1 = mn1;

            float s0 = 0.f, s1 = 0.f;
#pragma unroll
            for (int j = 0; j < 8; j++) {
                float p00 = fast_exp2(sacc[j][0] - mn0);
                float p01 = fast_exp2(sacc[j][1] - mn0);
                float p10 = fast_exp2(sacc[j][2] - mn1);
                float p11 = fast_exp2(sacc[j][3] - mn1);
                s0 += p00 + p01; s1 += p10 + p11;
                *(uint2*)&Phi[(r0)     * PSTR + j * 8 + 2 * qid] =
                    make_uint2(to_tf32(p00), to_tf32(p01));
                *(uint2*)&Phi[(r0 + 8) * PSTR + j * 8 + 2 * qid] =
                    make_uint2(to_tf32(p10), to_tf32(p11));
                oacc[j][0] *= c0; oacc[j][1] *= c0;
                oacc[j][2] *= c1; oacc[j][3] *= c1;
            }
            s0 += __shfl_xor_sync(0xffffffff, s0, 1);
            s0 += __shfl_xor_sync(0xffffffff, s0, 2);
            s1 += __shfl_xor_sync(0xffffffff, s1, 1);
            s1 += __shfl_xor_sync(0xffffffff, s1, 2);
            l0 = l0 * c0 + s0;
            l1 = l1 * c1 + s1;
        }

        if (t < 31) cp_wait1(); else cp_wait0();   // V(t) ready (K(t+1) may fly)
        __syncthreads();

        // ---- O += P @ V (single-pass tf32) ----
#pragma unroll
        for (int k = 0; k < 8; k++) {
            const int kk = k * 8;
            uint32_t ah[4];
            ah[0] = Phi[(r0)     * PSTR + kk + qid];
            ah[1] = Phi[(r0 + 8) * PSTR + kk + qid];
            ah[2] = Phi[(r0)     * PSTR + kk + qid + 4];
            ah[3] = Phi[(r0 + 8) * PSTR + kk + qid + 4];
#pragma unroll
            for (int j = 0; j < 8; j++) {
                int n = j * 8 + grp;
                uint32_t v0 = Vp[(kk + qid)     * VSTR + n];
                uint32_t v1 = Vp[(kk + qid + 4) * VSTR + n];
                mma_tf32(oacc[j][0], oacc[j][1], oacc[j][2], oacc[j][3],
                         ah[0], ah[1], ah[2], ah[3], v0, v1);
            }
        }
        __syncthreads();                 // all warps done reading V tile
        if (t + 1 < 32) stageV(t + 1);
    }

    // Epilogue: normalize, round to tf32 (out-proj GEMM needs no cvt)
    {
        float inv0 = 1.f / l0, inv1 = 1.f / l1;
        float* op0 = g_O + (size_t)(b * Sc + q0blk + r0) * Dc + h * HDc;
        float* op1 = g_O + (size_t)(b * Sc + q0blk + r0 + 8) * Dc + h * HDc;
#pragma unroll
        for (int j = 0; j < 8; j++) {
            *(float2*)&op0[j * 8 + 2 * qid] = make_float2(
                __uint_as_float(to_tf32(oacc[j][0] * inv0)),
                __uint_as_float(to_tf32(oacc[j][1] * inv0)));
            *(float2*)&op1[j * 8 + 2 * qid] = make_float2(
                __uint_as_float(to_tf32(oacc[j][2] * inv1)),
                __uint_as_float(to_tf32(oacc[j][3] * inv1)));
        }
    }
}

// ---------------------------------------------------------------------------
extern "C" void kernel_launch(void* const* d_in, const int* in_sizes, int n_in,
                              void* d_out, int out_size) {
    const float* X  = (const float*)d_in[0];
    const float* Wq = (const float*)d_in[1];
    const float* Wk = (const float*)d_in[2];
    const float* Wv = (const float*)d_in[3];
    const float* Wo = (const float*)d_in[4];
    float* out = (float*)d_out;

    uint32_t* QKV;
    float *Ob, *Xr, *Wqkv, *Wor;
    cudaGetSymbolAddress((void**)&QKV,  g_QKV);
    cudaGetSymbolAddress((void**)&Ob,   g_O);
    cudaGetSymbolAddress((void**)&Xr,   g_Xr);
    cudaGetSymbolAddress((void**)&Wqkv, g_Wqkv);
    cudaGetSymbolAddress((void**)&Wor,  g_Wor);

    cudaFuncSetAttribute(flash_attn_tc5, cudaFuncAttributeMaxDynamicSharedMemorySize, ATT_SMEM);

    const int M = Bc * Sc;         // 4096
    const size_t nX  = (size_t)M * Dc;
    const size_t nWq = (size_t)Dc * Dc;
    const size_t nWk = (size_t)Dc * KVHc * HDc;

    // tf32 pre-rounding; weights scattered into the concatenated [Wq|Wk|Wv] buffer
    round_tf32<<<(int)(nX  / 1024), 256>>>(X,  Xr,  nX);
    round_tf32_cat<<<(int)(nWq / 1024), 256>>>(Wq, Wqkv, Dc,          0,    nWq);
    round_tf32_cat<<<(int)(nWk / 1024), 256>>>(Wk, Wqkv, KVHc * HDc,  KOFF, nWk);
    round_tf32_cat<<<(int)(nWk / 1024), 256>>>(Wv, Wqkv, KVHc * HDc,  VOFF, nWk);
    round_tf32<<<(int)(nWq / 1024), 256>>>(Wo, Wor, nWq);

    // ONE fused QKV projection: [4096,2048] x [2048,3072] -> g_QKV (768 CTAs)
    tf32gemm_hi<<<dim3(NQKV / 128, M / 128), 256>>>(Xr, Wqkv, QKV, SCALE * LOG2E, M, NQKV, Dc);

    flash_attn_tc5<<<dim3(Sc / 64, Hc, Bc), 128, ATT_SMEM>>>();

    tf32gemm<<<dim3(Dc / 128, M / 128), 256>>>(Ob, Wor, out, M, Dc, Dc);
}

// round 17
// speedup vs baseline: 4.3088x; 1.0472x over previous
#include <cuda_runtime.h>
#include <cstdint>

// Problem constants
constexpr int Bc  = 2;
constexpr int Sc  = 2048;
constexpr int Dc  = 2048;
constexpr int Hc  = 32;
constexpr int KVHc = 8;
constexpr int HDc = 64;
constexpr float SCALE = 0.125f;   // 1/sqrt(64)
constexpr float LOG2E = 1.4426950408889634f;

constexpr int NQKV = Dc + 2 * KVHc * HDc;   // 3072 fused projection width
constexpr int KOFF = Dc;                    // K column offset in fused buffer
constexpr int VOFF = Dc + KVHc * HDc;       // V column offset

// Scratch (allocation-free rule: __device__ globals)
__device__ uint32_t g_QKV[(size_t)Bc * Sc * NQKV];   // tf32 bits: [Q | K | V] per row
__device__ float    g_O  [(size_t)Bc * Sc * Dc];     // tf32-rounded by epilogue
// tf32-rounded inputs (GEMM hot loops need no cvt)
__device__ float g_Xr  [(size_t)Bc * Sc * Dc];
__device__ float g_Wqkv[(size_t)Dc * NQKV];          // [Wq | Wk | Wv] columns
__device__ float g_Wor [(size_t)Dc * Dc];

// ---------------------------------------------------------------------------
// Common PTX helpers
// ---------------------------------------------------------------------------
__device__ __forceinline__ void cp16(void* smem, const void* gmem) {
    uint32_t s = (uint32_t)__cvta_generic_to_shared(smem);
    asm volatile("cp.async.cg.shared.global [%0], [%1], 16;\n" :: "r"(s), "l"(gmem));
}
__device__ __forceinline__ void cp_commit() { asm volatile("cp.async.commit_group;\n"); }
__device__ __forceinline__ void cp_wait0()  { asm volatile("cp.async.wait_group 0;\n"); }
__device__ __forceinline__ void cp_wait1()  { asm volatile("cp.async.wait_group 1;\n"); }

__device__ __forceinline__ uint32_t to_tf32(float f) {
    uint32_t r;
    asm("cvt.rna.tf32.f32 %0, %1;" : "=r"(r) : "f"(f));
    return r;
}

__device__ __forceinline__ void mma_tf32(float& c0, float& c1, float& c2, float& c3,
                                         uint32_t a0, uint32_t a1, uint32_t a2, uint32_t a3,
                                         uint32_t b0, uint32_t b1) {
    asm volatile(
        "mma.sync.aligned.m16n8k8.row.col.f32.tf32.tf32.f32 "
        "{%0,%1,%2,%3}, {%4,%5,%6,%7}, {%8,%9}, {%0,%1,%2,%3};\n"
        : "+f"(c0), "+f"(c1), "+f"(c2), "+f"(c3)
        : "r"(a0), "r"(a1), "r"(a2), "r"(a3), "r"(b0), "r"(b1));
}

// Fast 2^y for y <= 0 (FMA pipe only, no MUFU). Rel err ~4e-5.
__device__ __forceinline__ float fast_exp2(float y) {
    y = fmaxf(y, -80.f);
    float t = y + 12582912.f;
    int k = __float_as_int(t) - 0x4B400000;
    float f = y - (t - 12582912.f);
    float r = fmaf(f, 0.0096181291f, 0.0555041087f);
    r = fmaf(f, r, 0.2402265069f);
    r = fmaf(f, r, 0.6931471806f);
    r = fmaf(f, r, 1.0f);
    return __int_as_float(__float_as_int(r) + (k << 23));
}

// ---------------------------------------------------------------------------
// tf32 rounding pre-passes
// ---------------------------------------------------------------------------
__global__ __launch_bounds__(256) void round_tf32(const float* __restrict__ in,
                                                  float* __restrict__ out, size_t n) {
    size_t i = ((size_t)blockIdx.x * 256 + threadIdx.x) * 4;
    if (i >= n) return;
    float4 v = *(const float4*)(in + i);
    v.x = __uint_as_float(to_tf32(v.x));
    v.y = __uint_as_float(to_tf32(v.y));
    v.z = __uint_as_float(to_tf32(v.z));
    v.w = __uint_as_float(to_tf32(v.w));
    *(float4*)(out + i) = v;
}

// Round + scatter rows into the concatenated weight buffer:
// in [rows x ncols] row-major -> out[row * NQKV + coloff + col]
__global__ __launch_bounds__(256) void round_tf32_cat(const float* __restrict__ in,
                                                      float* __restrict__ out,
                                                      int ncols, int coloff, size_t n) {
    size_t i = ((size_t)blockIdx.x * 256 + threadIdx.x) * 4;
    if (i >= n) return;
    float4 v = *(const float4*)(in + i);
    v.x = __uint_as_float(to_tf32(v.x));
    v.y = __uint_as_float(to_tf32(v.y));
    v.z = __uint_as_float(to_tf32(v.z));
    v.w = __uint_as_float(to_tf32(v.w));
    int row = (int)(i / ncols);
    int col = (int)(i % ncols);
    *(float4*)(out + (size_t)row * NQKV + coloff + col) = v;
}

// ---------------------------------------------------------------------------
// TF32 GEMM core (128x128 tile, BK=16, 8 warps, m16n8k8).
// Inputs MUST be pre-rounded to tf32 -> no cvt in the hot loop.
// ---------------------------------------------------------------------------
constexpr int ASTRIDE = 20;
constexpr int BSTRIDE = 136;
constexpr int ABUF = 128 * ASTRIDE;
constexpr int BBUF = 16 * BSTRIDE;

#define GEMM_BODY                                                                   \
    __shared__ float As[2][ABUF];                                                   \
    __shared__ float Bs[2][BBUF];                                                   \
    const int tid  = threadIdx.x;                                                   \
    const int warp = tid >> 5;                                                      \
    const int lane = tid & 31;                                                      \
    const int grp  = lane >> 2;                                                     \
    const int qid  = lane & 3;                                                      \
    const int warpM = warp >> 2;                                                    \
    const int warpN = warp & 3;                                                     \
    const int bx = blockIdx.x;                                                      \
    const int by = blockIdx.y;                                                      \
    const int numTiles = K / 16;                                                    \
    auto load_tile = [&](int t, int s) {                                            \
        int k0 = t * 16;                                                            \
        {                                                                           \
            int r = tid >> 2, cc = tid & 3;                                         \
            cp16(&As[s][r * ASTRIDE + cc * 4],                                      \
                 A + (size_t)(by * 128 + r) * K + k0 + cc * 4);                     \
            r = (tid + 256) >> 2; cc = (tid + 256) & 3;                             \
            cp16(&As[s][r * ASTRIDE + cc * 4],                                      \
                 A + (size_t)(by * 128 + r) * K + k0 + cc * 4);                     \
        }                                                                           \
        {                                                                           \
            int r = tid >> 5, cc = tid & 31;                                        \
            cp16(&Bs[s][r * BSTRIDE + cc * 4],                                      \
                 Bm + (size_t)(k0 + r) * N + bx * 128 + cc * 4);                    \
            r = (tid + 256) >> 5; cc = (tid + 256) & 31;                            \
            cp16(&Bs[s][r * BSTRIDE + cc * 4],                                      \
                 Bm + (size_t)(k0 + r) * N + bx * 128 + cc * 4);                    \
        }                                                                           \
        cp_commit();                                                                \
    };                                                                              \
    float acc[4][4][4];                                                             \
    _Pragma("unroll")                                                               \
    for (int i = 0; i < 4; i++)                                                     \
        _Pragma("unroll")                                                           \
        for (int j = 0; j < 4; j++)                                                 \
            _Pragma("unroll")                                                       \
            for (int r = 0; r < 4; r++) acc[i][j][r] = 0.f;                         \
    load_tile(0, 0);                                                                \
    for (int t = 0; t < numTiles; t++) {                                            \
        cp_wait0();                                                                 \
        __syncthreads();                                                            \
        if (t + 1 < numTiles) load_tile(t + 1, (t + 1) & 1);                        \
        const uint32_t* Asb = (const uint32_t*)As[t & 1];                           \
        const uint32_t* Bsb = (const uint32_t*)Bs[t & 1];                           \
        _Pragma("unroll")                                                           \
        for (int kk = 0; kk < 16; kk += 8) {                                        \
            uint32_t af[4][4];                                                      \
            _Pragma("unroll")                                                       \
            for (int i = 0; i < 4; i++) {                                           \
                int mr = warpM * 64 + i * 16 + grp;                                 \
                af[i][0] = Asb[(mr)     * ASTRIDE + kk + qid];                      \
                af[i][1] = Asb[(mr + 8) * ASTRIDE + kk + qid];                      \
                af[i][2] = Asb[(mr)     * ASTRIDE + kk + qid + 4];                  \
                af[i][3] = Asb[(mr + 8) * ASTRIDE + kk + qid + 4];                  \
            }                                                                       \
            uint32_t bf[4][2];                                                      \
            _Pragma("unroll")                                                       \
            for (int j = 0; j < 4; j++) {                                           \
                int nc = warpN * 32 + j * 8 + grp;                                  \
                bf[j][0] = Bsb[(kk + qid)     * BSTRIDE + nc];                      \
                bf[j][1] = Bsb[(kk + qid + 4) * BSTRIDE + nc];                      \
            }                                                                       \
            _Pragma("unroll")                                                       \
            for (int i = 0; i < 4; i++)                                             \
                _Pragma("unroll")                                                   \
                for (int j = 0; j < 4; j++)                                         \
                    mma_tf32(acc[i][j][0], acc[i][j][1], acc[i][j][2], acc[i][j][3],\
                             af[i][0], af[i][1], af[i][2], af[i][3],                \
                             bf[j][0], bf[j][1]);                                   \
        }                                                                           \
        __syncthreads();                                                            \
    }

__global__ __launch_bounds__(256) void tf32gemm(const float* __restrict__ A,
                                                const float* __restrict__ Bm,
                                                float* __restrict__ C,
                                                int M, int N, int K) {
    GEMM_BODY
#pragma unroll
    for (int i = 0; i < 4; i++) {
        int mr = by * 128 + warpM * 64 + i * 16 + grp;
#pragma unroll
        for (int j = 0; j < 4; j++) {
            int nc = bx * 128 + warpN * 32 + j * 8 + 2 * qid;
            *(float2*)&C[(size_t)mr * N + nc]       = make_float2(acc[i][j][0], acc[i][j][1]);
            *(float2*)&C[(size_t)(mr + 8) * N + nc] = make_float2(acc[i][j][2], acc[i][j][3]);
        }
    }
}

// Fused QKV epilogue: tf32 hi bits; Q columns (bx < Dc/128) get qscale prescale.
__global__ __launch_bounds__(256) void tf32gemm_hi(const float* __restrict__ A,
                                                   const float* __restrict__ Bm,
                                                   uint32_t* __restrict__ Chi,
                                                   float qscale,
                                                   int M, int N, int K) {
    GEMM_BODY
    const float prescale = (bx < Dc / 128) ? qscale : 1.f;
#pragma unroll
    for (int i = 0; i < 4; i++) {
        int mr = by * 128 + warpM * 64 + i * 16 + grp;
#pragma unroll
        for (int j = 0; j < 4; j++) {
            int nc = bx * 128 + warpN * 32 + j * 8 + 2 * qid;
            *(uint2*)&Chi[(size_t)mr * N + nc] =
                make_uint2(to_tf32(acc[i][j][0] * prescale), to_tf32(acc[i][j][1] * prescale));
            *(uint2*)&Chi[(size_t)(mr + 8) * N + nc] =
                make_uint2(to_tf32(acc[i][j][2] * prescale), to_tf32(acc[i][j][3] * prescale));
        }
    }
}

// ---------------------------------------------------------------------------
// Tensor-core flash attention, single-pass tf32, fused QKV buffer.
// CTA: 128 queries x 1 head, 4 warps, warp tile M=32 (each K/V fragment feeds
// 2 MMAs -> smem crossbar traffic per FLOP halves vs M=16).
// K(t+1) prefetched during softmax+PV; V(t+1) after PV; split wait_groups.
// ---------------------------------------------------------------------------
constexpr int KSTR = 68;   // u32 stride per K row: conflict-free
constexpr int VSTR = 72;   // u32 stride per V row: conflict-free
constexpr int PSTR = 72;   // u32 stride per P row: STS.64-clean
constexpr int QPB  = 128;  // queries per block
constexpr int ATT_SMEM = (64 * KSTR + 64 * VSTR + QPB * PSTR) * 4;  // 72704 B

__global__ __launch_bounds__(128) void flash_attn_tc6() {
    extern __shared__ uint32_t smu[];
    uint32_t* Kp  = smu;
    uint32_t* Vp  = Kp + 64 * KSTR;
    uint32_t* Phi = Vp + 64 * VSTR;

    const int tid  = threadIdx.x;
    const int warp = tid >> 5;
    const int lane = tid & 31;
    const int grp  = lane >> 2;
    const int qid  = lane & 3;
    const int h = blockIdx.y, b = blockIdx.z;
    const int g = h >> 2;
    const int q0blk = blockIdx.x * QPB;

    const int r0 = warp * 32 + grp;   // warp owns rows r0+{0,8,16,24}

    auto stageK = [&](int t) {
#pragma unroll
        for (int i = 0; i < 8; i++) {
            int c = tid + i * 128;            // 0..1023 chunks of 16B
            int row = c >> 4, cc = (c & 15) * 4;
            size_t gb = (size_t)(b * Sc + t * 64 + row) * NQKV + KOFF + g * HDc + cc;
            cp16(&Kp[row * KSTR + cc], g_QKV + gb);
        }
        cp_commit();
    };
    auto stageV = [&](int t) {
#pragma unroll
        for (int i = 0; i < 8; i++) {
            int c = tid + i * 128;
            int row = c >> 4, cc = (c & 15) * 4;
            size_t gb = (size_t)(b * Sc + t * 64 + row) * NQKV + VOFF + g * HDc + cc;
            cp16(&Vp[row * VSTR + cc], g_QKV + gb);
        }
        cp_commit();
    };

    // Q fragments (prescaled tf32 hi), 2 row-pair sets, loop-invariant
    uint32_t qh[2][8][4];
#pragma unroll
    for (int mi = 0; mi < 2; mi++) {
        const size_t base = (size_t)(b * Sc + q0blk + r0 + 16 * mi) * NQKV + h * HDc;
        const size_t row8 = (size_t)8 * NQKV;
#pragma unroll
        for (int k = 0; k < 8; k++) {
            int c0 = k * 8 + qid;
            qh[mi][k][0] = g_QKV[base + c0];
            qh[mi][k][1] = g_QKV[base + row8 + c0];
            qh[mi][k][2] = g_QKV[base + c0 + 4];
            qh[mi][k][3] = g_QKV[base + row8 + c0 + 4];
        }
    }

    float oacc[2][8][4];
#pragma unroll
    for (int mi = 0; mi < 2; mi++)
#pragma unroll
        for (int j = 0; j < 8; j++)
#pragma unroll
            for (int r = 0; r < 4; r++) oacc[mi][j][r] = 0.f;
    float mx[4] = {-1e30f, -1e30f, -1e30f, -1e30f};
    float li[4] = {0.f, 0.f, 0.f, 0.f};

    stageK(0);
    stageV(0);

    for (int t = 0; t < 32; t++) {
        cp_wait1();          // K(t) ready (V(t) may still be in flight)
        __syncthreads();

        // ---- S = Q @ K^T (single-pass tf32, each K frag used by 2 MMAs) ----
        float sacc[2][8][4];
#pragma unroll
        for (int mi = 0; mi < 2; mi++)
#pragma unroll
            for (int j = 0; j < 8; j++)
#pragma unroll
                for (int r = 0; r < 4; r++) sacc[mi][j][r] = 0.f;

#pragma unroll
        for (int k = 0; k < 8; k++) {
            const int kk = k * 8;
#pragma unroll
            for (int j = 0; j < 8; j++) {
                int n = j * 8 + grp;
                uint32_t b0 = Kp[n * KSTR + kk + qid];
                uint32_t b1 = Kp[n * KSTR + kk + qid + 4];
                mma_tf32(sacc[0][j][0], sacc[0][j][1], sacc[0][j][2], sacc[0][j][3],
                         qh[0][k][0], qh[0][k][1], qh[0][k][2], qh[0][k][3], b0, b1);
                mma_tf32(sacc[1][j][0], sacc[1][j][1], sacc[1][j][2], sacc[1][j][3],
                         qh[1][k][0], qh[1][k][1], qh[1][k][2], qh[1][k][3], b0, b1);
            }
        }
        __syncthreads();                 // all warps done reading K tile
        if (t + 1 < 32) stageK(t + 1);   // K prefetch hides behind softmax+PV

        // ---- online softmax (log2 domain); P (tf32) -> Phi ----
        {
#pragma unroll
            for (int mi = 0; mi < 2; mi++) {
                float nx0 = -1e30f, nx1 = -1e30f;
#pragma unroll
                for (int j = 0; j < 8; j++) {
                    nx0 = fmaxf(nx0, fmaxf(sacc[mi][j][0], sacc[mi][j][1]));
                    nx1 = fmaxf(nx1, fmaxf(sacc[mi][j][2], sacc[mi][j][3]));
                }
                nx0 = fmaxf(nx0, __shfl_xor_sync(0xffffffff, nx0, 1));
                nx0 = fmaxf(nx0, __shfl_xor_sync(0xffffffff, nx0, 2));
                nx1 = fmaxf(nx1, __shfl_xor_sync(0xffffffff, nx1, 1));
                nx1 = fmaxf(nx1, __shfl_xor_sync(0xffffffff, nx1, 2));

                float mn0 = fmaxf(mx[2 * mi], nx0), mn1 = fmaxf(mx[2 * mi + 1], nx1);
                float c0 = fast_exp2(mx[2 * mi] - mn0), c1 = fast_exp2(mx[2 * mi + 1] - mn1);
                mx[2 * mi] = mn0; mx[2 * mi + 1] = mn1;

                float s0 = 0.f, s1 = 0.f;
                const int pr0 = r0 + 16 * mi;
#pragma unroll
                for (int j = 0; j < 8; j++) {
                    float p00 = fast_exp2(sacc[mi][j][0] - mn0);
                    float p01 = fast_exp2(sacc[mi][j][1] - mn0);
                    float p10 = fast_exp2(sacc[mi][j][2] - mn1);
                    float p11 = fast_exp2(sacc[mi][j][3] - mn1);
                    s0 += p00 + p01; s1 += p10 + p11;
                    *(uint2*)&Phi[(pr0)     * PSTR + j * 8 + 2 * qid] =
                        make_uint2(to_tf32(p00), to_tf32(p01));
                    *(uint2*)&Phi[(pr0 + 8) * PSTR + j * 8 + 2 * qid] =
                        make_uint2(to_tf32(p10), to_tf32(p11));
                    oacc[mi][j][0] *= c0; oacc[mi][j][1] *= c0;
                    oacc[mi][j][2] *= c1; oacc[mi][j][3] *= c1;
                }
                s0 += __shfl_xor_sync(0xffffffff, s0, 1);
                s0 += __shfl_xor_sync(0xffffffff, s0, 2);
                s1 += __shfl_xor_sync(0xffffffff, s1, 1);
                s1 += __shfl_xor_sync(0xffffffff, s1, 2);
                li[2 * mi]     = li[2 * mi]     * c0 + s0;
                li[2 * mi + 1] = li[2 * mi + 1] * c1 + s1;
            }
        }

        if (t < 31) cp_wait1(); else cp_wait0();   // V(t) ready (K(t+1) may fly)
        __syncthreads();

        // ---- O += P @ V (single-pass tf32, each V frag used by 2 MMAs) ----
#pragma unroll
        for (int k = 0; k < 8; k++) {
            const int kk = k * 8;
            uint32_t a0[4], a1[4];
            a0[0] = Phi[(r0)      * PSTR + kk + qid];
            a0[1] = Phi[(r0 + 8)  * PSTR + kk + qid];
            a0[2] = Phi[(r0)      * PSTR + kk + qid + 4];
            a0[3] = Phi[(r0 + 8)  * PSTR + kk + qid + 4];
            a1[0] = Phi[(r0 + 16) * PSTR + kk + qid];
            a1[1] = Phi[(r0 + 24) * PSTR + kk + qid];
            a1[2] = Phi[(r0 + 16) * PSTR + kk + qid + 4];
            a1[3] = Phi[(r0 + 24) * PSTR + kk + qid + 4];
#pragma unroll
            for (int j = 0; j < 8; j++) {
                int n = j * 8 + grp;
                uint32_t v0 = Vp[(kk + qid)     * VSTR + n];
                uint32_t v1 = Vp[(kk + qid + 4) * VSTR + n];
                mma_tf32(oacc[0][j][0], oacc[0][j][1], oacc[0][j][2], oacc[0][j][3],
                         a0[0], a0[1], a0[2], a0[3], v0, v1);
                mma_tf32(oacc[1][j][0], oacc[1][j][1], oacc[1][j][2], oacc[1][j][3],
                         a1[0], a1[1], a1[2], a1[3], v0, v1);
            }
        }
        __syncthreads();                 // all warps done reading V tile
        if (t + 1 < 32) stageV(t + 1);
    }

    // Epilogue: normalize, round to tf32 (out-proj GEMM needs no cvt)
#pragma unroll
    for (int mi = 0; mi < 2; mi++) {
        float inv0 = 1.f / li[2 * mi], inv1 = 1.f / li[2 * mi + 1];
        float* op0 = g_O + (size_t)(b * Sc + q0blk + r0 + 16 * mi) * Dc + h * HDc;
        float* op1 = op0 + (size_t)8 * Dc;
#pragma unroll
        for (int j = 0; j < 8; j++) {
            *(float2*)&op0[j * 8 + 2 * qid] = make_float2(
                __uint_as_float(to_tf32(oacc[mi][j][0] * inv0)),
                __uint_as_float(to_tf32(oacc[mi][j][1] * inv0)));
            *(float2*)&op1[j * 8 + 2 * qid] = make_float2(
                __uint_as_float(to_tf32(oacc[mi][j][2] * inv1)),
                __uint_as_float(to_tf32(oacc[mi][j][3] * inv1)));
        }
    }
}

// ---------------------------------------------------------------------------
extern "C" void kernel_launch(void* const* d_in, const int* in_sizes, int n_in,
                              void* d_out, int out_size) {
    const float* X  = (const float*)d_in[0];
    const float* Wq = (const float*)d_in[1];
    const float* Wk = (const float*)d_in[2];
    const float* Wv = (const float*)d_in[3];
    const float* Wo = (const float*)d_in[4];
    float* out = (float*)d_out;

    uint32_t* QKV;
    float *Ob, *Xr, *Wqkv, *Wor;
    cudaGetSymbolAddress((void**)&QKV,  g_QKV);
    cudaGetSymbolAddress((void**)&Ob,   g_O);
    cudaGetSymbolAddress((void**)&Xr,   g_Xr);
    cudaGetSymbolAddress((void**)&Wqkv, g_Wqkv);
    cudaGetSymbolAddress((void**)&Wor,  g_Wor);

    cudaFuncSetAttribute(flash_attn_tc6, cudaFuncAttributeMaxDynamicSharedMemorySize, ATT_SMEM);

    const int M = Bc * Sc;         // 4096
    const size_t nX  = (size_t)M * Dc;
    const size_t nWq = (size_t)Dc * Dc;
    const size_t nWk = (size_t)Dc * KVHc * HDc;

    // tf32 pre-rounding; weights scattered into the concatenated [Wq|Wk|Wv] buffer
    round_tf32<<<(int)(nX  / 1024), 256>>>(X,  Xr,  nX);
    round_tf32_cat<<<(int)(nWq / 1024), 256>>>(Wq, Wqkv, Dc,          0,    nWq);
    round_tf32_cat<<<(int)(nWk / 1024), 256>>>(Wk, Wqkv, KVHc * HDc,  KOFF, nWk);
    round_tf32_cat<<<(int)(nWk / 1024), 256>>>(Wv, Wqkv, KVHc * HDc,  VOFF, nWk);
    round_tf32<<<(int)(nWq / 1024), 256>>>(Wo, Wor, nWq);

    // ONE fused QKV projection: [4096,2048] x [2048,3072] -> g_QKV (768 CTAs)
    tf32gemm_hi<<<dim3(NQKV / 128, M / 128), 256>>>(Xr, Wqkv, QKV, SCALE * LOG2E, M, NQKV, Dc);

    flash_attn_tc6<<<dim3(Sc / QPB, Hc, Bc), 128, ATT_SMEM>>>();

    tf32gemm<<<dim3(Dc / 128, M / 128), 256>>>(Ob, Wor, out, M, Dc, Dc);
}